// round 3
// baseline (speedup 1.0000x reference)
#include <cuda_runtime.h>
#include <cstdint>

#define BB   4
#define LL   1024
#define DMD  2048
#define HH   32
#define KVH  4
#define HDD  128
#define GG   (HH / KVH)
#define EE   16
#define TOPKK 8
#define MII  128
#define NTOK (BB * LL)
#define EPSF 1e-6f

// ---------------- scratch (device globals; no allocation allowed) ------------
__device__ float g_h  [NTOK * DMD];        // normed attn input
__device__ float g_q  [NTOK * HH  * HDD];  // q proj (token-major)
__device__ float g_k  [NTOK * KVH * HDD];
__device__ float g_v  [NTOK * KVH * HDD];
__device__ float g_qt [NTOK * HH  * HDD];  // (b,h,l,d)
__device__ float g_kt [NTOK * KVH * HDD];
__device__ float g_vt [NTOK * KVH * HDD];
__device__ float g_ao [NTOK * HH  * HDD];  // attention output (token-major)
__device__ float g_hm [NTOK * DMD];        // normed mlp input
__device__ float g_wd [NTOK * EE];         // dense router weights
__device__ float g_actall[NTOK * EE * MII];// scaled silu(gate)*up, [row][e*128+k]

// ---------------- generic SGEMM: C = A(MxK) * B(NxK)^T, fused epilogues ------
// mode 0: C = acc
// mode 1: C = aux + acc                 (residual add)
__global__ __launch_bounds__(256) void sgemm_bt(
    const float* __restrict__ A, const float* __restrict__ Bw,
    float* __restrict__ C, int M, int N, int K,
    int mode, const float* __restrict__ aux)
{
    __shared__ float As[16][68];
    __shared__ float Bs[16][68];
    const int tid = threadIdx.x;
    const int tx  = tid & 15;
    const int ty  = tid >> 4;
    const int lr  = tid >> 2;          // 0..63
    const int lc  = (tid & 3) << 2;    // 0,4,8,12
    const int row0 = blockIdx.y * 64;
    const int col0 = blockIdx.x * 64;

    const float* Ap = A  + (size_t)(row0 + lr) * K + lc;
    const float* Bp = Bw + (size_t)(col0 + lr) * K + lc;

    float acc[4][4] = {};
    for (int k0 = 0; k0 < K; k0 += 16) {
        float4 av = *reinterpret_cast<const float4*>(Ap + k0);
        float4 bv = *reinterpret_cast<const float4*>(Bp + k0);
        As[lc + 0][lr] = av.x; As[lc + 1][lr] = av.y;
        As[lc + 2][lr] = av.z; As[lc + 3][lr] = av.w;
        Bs[lc + 0][lr] = bv.x; Bs[lc + 1][lr] = bv.y;
        Bs[lc + 2][lr] = bv.z; Bs[lc + 3][lr] = bv.w;
        __syncthreads();
#pragma unroll
        for (int k = 0; k < 16; k++) {
            float4 a4 = *reinterpret_cast<const float4*>(&As[k][ty * 4]);
            float4 b4 = *reinterpret_cast<const float4*>(&Bs[k][tx * 4]);
            float a[4] = {a4.x, a4.y, a4.z, a4.w};
            float b[4] = {b4.x, b4.y, b4.z, b4.w};
#pragma unroll
            for (int i = 0; i < 4; i++)
#pragma unroll
                for (int j = 0; j < 4; j++)
                    acc[i][j] = fmaf(a[i], b[j], acc[i][j]);
        }
        __syncthreads();
    }

#pragma unroll
    for (int i = 0; i < 4; i++) {
        int row = row0 + ty * 4 + i;
        size_t base = (size_t)row * N + col0 + tx * 4;
        float4 v;
        v.x = acc[i][0]; v.y = acc[i][1]; v.z = acc[i][2]; v.w = acc[i][3];
        if (mode == 1) {
            float4 r = *reinterpret_cast<const float4*>(aux + base);
            v.x += r.x; v.y += r.y; v.z += r.z; v.w += r.w;
        }
        *reinterpret_cast<float4*>(C + base) = v;
    }
}

// -------- MoE fused gate+up: act[row][e*128+col] = w(row,e)*silu(g)*u --------
__global__ __launch_bounds__(256) void moe_gateup(
    const float* __restrict__ A, const float* __restrict__ Gw,
    const float* __restrict__ Uw, float* __restrict__ Act,
    const float* __restrict__ wd)
{
    __shared__ float As[16][68];
    __shared__ float Gs[16][68];
    __shared__ float Us[16][68];
    const int e   = blockIdx.z;
    const int tid = threadIdx.x;
    const int tx  = tid & 15;
    const int ty  = tid >> 4;
    const int lr  = tid >> 2;
    const int lc  = (tid & 3) << 2;
    const int row0 = blockIdx.y * 64;
    const int col0 = blockIdx.x * 64;

    const float* Ap = A  + (size_t)(row0 + lr) * DMD + lc;
    const float* Gp = Gw + (size_t)e * MII * DMD + (size_t)(col0 + lr) * DMD + lc;
    const float* Up = Uw + (size_t)e * MII * DMD + (size_t)(col0 + lr) * DMD + lc;

    float accg[4][4] = {};
    float accu[4][4] = {};
    for (int k0 = 0; k0 < DMD; k0 += 16) {
        float4 av = *reinterpret_cast<const float4*>(Ap + k0);
        float4 gv = *reinterpret_cast<const float4*>(Gp + k0);
        float4 uv = *reinterpret_cast<const float4*>(Up + k0);
        As[lc + 0][lr] = av.x; As[lc + 1][lr] = av.y;
        As[lc + 2][lr] = av.z; As[lc + 3][lr] = av.w;
        Gs[lc + 0][lr] = gv.x; Gs[lc + 1][lr] = gv.y;
        Gs[lc + 2][lr] = gv.z; Gs[lc + 3][lr] = gv.w;
        Us[lc + 0][lr] = uv.x; Us[lc + 1][lr] = uv.y;
        Us[lc + 2][lr] = uv.z; Us[lc + 3][lr] = uv.w;
        __syncthreads();
#pragma unroll
        for (int k = 0; k < 16; k++) {
            float4 a4 = *reinterpret_cast<const float4*>(&As[k][ty * 4]);
            float4 g4 = *reinterpret_cast<const float4*>(&Gs[k][tx * 4]);
            float4 u4 = *reinterpret_cast<const float4*>(&Us[k][tx * 4]);
            float a[4] = {a4.x, a4.y, a4.z, a4.w};
            float g[4] = {g4.x, g4.y, g4.z, g4.w};
            float u[4] = {u4.x, u4.y, u4.z, u4.w};
#pragma unroll
            for (int i = 0; i < 4; i++)
#pragma unroll
                for (int j = 0; j < 4; j++) {
                    accg[i][j] = fmaf(a[i], g[j], accg[i][j]);
                    accu[i][j] = fmaf(a[i], u[j], accu[i][j]);
                }
        }
        __syncthreads();
    }

#pragma unroll
    for (int i = 0; i < 4; i++) {
        int row = row0 + ty * 4 + i;
        float w = wd[(size_t)row * EE + e];
        size_t base = (size_t)row * (EE * MII) + e * MII + col0 + tx * 4;
        float4 v;
#pragma unroll
        for (int j = 0; j < 4; j++) {
            float gg = accg[i][j];
            float s  = gg / (1.f + __expf(-gg));
            (&v.x)[j] = w * s * accu[i][j];
        }
        *reinterpret_cast<float4*>(Act + base) = v;
    }
}

// -------- MoE fused down: out += sum_e act_e @ dw_e^T  (K = 16*128) ----------
__global__ __launch_bounds__(256) void moe_down(
    const float* __restrict__ Act, const float* __restrict__ Dw,
    float* __restrict__ C)
{
    __shared__ float As[16][68];
    __shared__ float Bs[16][68];
    const int tid = threadIdx.x;
    const int tx  = tid & 15;
    const int ty  = tid >> 4;
    const int lr  = tid >> 2;
    const int lc  = (tid & 3) << 2;
    const int row0 = blockIdx.y * 64;
    const int col0 = blockIdx.x * 64;
    const int KTOT = EE * MII;   // 2048

    const float* Ap = Act + (size_t)(row0 + lr) * KTOT + lc;

    float acc[4][4] = {};
    for (int k0 = 0; k0 < KTOT; k0 += 16) {
        int e    = k0 >> 7;          // expert index
        int koff = k0 & 127;         // k within expert
        const float* Bp = Dw + (size_t)e * DMD * MII
                             + (size_t)(col0 + lr) * MII + koff + lc;
        float4 av = *reinterpret_cast<const float4*>(Ap + k0);
        float4 bv = *reinterpret_cast<const float4*>(Bp);
        As[lc + 0][lr] = av.x; As[lc + 1][lr] = av.y;
        As[lc + 2][lr] = av.z; As[lc + 3][lr] = av.w;
        Bs[lc + 0][lr] = bv.x; Bs[lc + 1][lr] = bv.y;
        Bs[lc + 2][lr] = bv.z; Bs[lc + 3][lr] = bv.w;
        __syncthreads();
#pragma unroll
        for (int k = 0; k < 16; k++) {
            float4 a4 = *reinterpret_cast<const float4*>(&As[k][ty * 4]);
            float4 b4 = *reinterpret_cast<const float4*>(&Bs[k][tx * 4]);
            float a[4] = {a4.x, a4.y, a4.z, a4.w};
            float b[4] = {b4.x, b4.y, b4.z, b4.w};
#pragma unroll
            for (int i = 0; i < 4; i++)
#pragma unroll
                for (int j = 0; j < 4; j++)
                    acc[i][j] = fmaf(a[i], b[j], acc[i][j]);
        }
        __syncthreads();
    }

#pragma unroll
    for (int i = 0; i < 4; i++) {
        int row = row0 + ty * 4 + i;
        size_t base = (size_t)row * DMD + col0 + tx * 4;
        float4 c = *reinterpret_cast<const float4*>(C + base);
        c.x += acc[i][0]; c.y += acc[i][1];
        c.z += acc[i][2]; c.w += acc[i][3];
        *reinterpret_cast<float4*>(C + base) = c;
    }
}

// ---------------- row RMSNorm over DM ----------------------------------------
__global__ __launch_bounds__(256) void rmsnorm_kernel(
    const float* __restrict__ x, const float* __restrict__ w, float* __restrict__ y)
{
    int row = blockIdx.x;
    const float* xr = x + (size_t)row * DMD;
    float ss = 0.f;
    for (int d = threadIdx.x; d < DMD; d += 256) { float v = xr[d]; ss += v * v; }
    __shared__ float red[8];
#pragma unroll
    for (int o = 16; o > 0; o >>= 1) ss += __shfl_xor_sync(~0u, ss, o);
    if ((threadIdx.x & 31) == 0) red[threadIdx.x >> 5] = ss;
    __syncthreads();
    if (threadIdx.x < 8) {
        float t = red[threadIdx.x];
#pragma unroll
        for (int o = 4; o > 0; o >>= 1) t += __shfl_xor_sync(0xffu, t, o);
        if (threadIdx.x == 0) red[0] = t;
    }
    __syncthreads();
    float scale = rsqrtf(red[0] / (float)DMD + EPSF);
    for (int d = threadIdx.x; d < DMD; d += 256)
        y[(size_t)row * DMD + d] = xr[d] * scale * w[d];
}

// -------- per-head RMSNorm + RoPE + transpose to (b,head,l,d); V transpose ---
__global__ __launch_bounds__(128) void qkv_post(
    const float* __restrict__ cosb, const float* __restrict__ sinb,
    const float* __restrict__ qn_w, const float* __restrict__ kn_w)
{
    int b = blockIdx.z, l = blockIdx.y, rr = blockIdx.x;
    int d = threadIdx.x;
    int n = b * LL + l;
    __shared__ float buf[HDD];
    __shared__ float red[4];

    const float* src; float* dst; const float* nw;
    if (rr < HH) {
        src = g_q + (size_t)n * HH * HDD + rr * HDD;
        dst = g_qt + ((size_t)(b * HH + rr) * LL + l) * HDD;
        nw = qn_w;
    } else if (rr < HH + KVH) {
        int kv = rr - HH;
        src = g_k + (size_t)n * KVH * HDD + kv * HDD;
        dst = g_kt + ((size_t)(b * KVH + kv) * LL + l) * HDD;
        nw = kn_w;
    } else {
        int kv = rr - HH - KVH;
        g_vt[((size_t)(b * KVH + kv) * LL + l) * HDD + d] =
            g_v[(size_t)n * KVH * HDD + kv * HDD + d];
        return;
    }
    float v = src[d];
    float ss = v * v;
#pragma unroll
    for (int o = 16; o > 0; o >>= 1) ss += __shfl_xor_sync(~0u, ss, o);
    if ((d & 31) == 0) red[d >> 5] = ss;
    __syncthreads();
    float tot = red[0] + red[1] + red[2] + red[3];
    float nv = v * rsqrtf(tot / (float)HDD + EPSF) * nw[d];
    buf[d] = nv;
    __syncthreads();
    float other = (d < HDD / 2) ? -buf[d + HDD / 2] : buf[d - HDD / 2];
    float c = cosb[(size_t)n * HDD + d];
    float s = sinb[(size_t)n * HDD + d];
    dst[d] = c * nv + s * other;
}

// ---------------- fp32 flash attention (causal, GQA) -------------------------
#define AM 32
#define AN 32
#define QSTR 132
#define ATTN_SMEM ((AM * QSTR + AN * QSTR + AN * HDD) * 4)

__global__ __launch_bounds__(256) void attn_kernel()
{
    extern __shared__ float sm[];
    float* Qs = sm;                  // AM x QSTR
    float* Ks = Qs + AM * QSTR;      // AN x QSTR
    float* Vs = Ks + AN * QSTR;      // AN x HDD

    const int tid = threadIdx.x;
    const int b = blockIdx.z, h = blockIdx.y;
    const int q0 = blockIdx.x * AM;
    const int kv = h / GG;
    const float SCALE = 0.08838834764831845f;  // 1/sqrt(128)

    const float* Qg = g_qt + ((size_t)(b * HH + h) * LL + q0) * HDD;
    const float* Kg = g_kt + ((size_t)(b * KVH + kv) * LL) * HDD;
    const float* Vg = g_vt + ((size_t)(b * KVH + kv) * LL) * HDD;

#pragma unroll
    for (int i = 0; i < 16; i++) {
        int e = tid + i * 256;
        int r = e >> 7, d = e & 127;
        Qs[r * QSTR + d] = Qg[(size_t)r * HDD + d] * SCALE;
    }

    const int r = tid >> 3;      // q row 0..31
    const int g = tid & 7;       // group 0..7
    const int d0 = g * 16;

    float m_r = -1e30f, l_r = 0.f;
    float acc[16];
#pragma unroll
    for (int t = 0; t < 16; t++) acc[t] = 0.f;

    const int ntile = q0 / AN + 1;
    for (int kt = 0; kt < ntile; kt++) {
        int k0 = kt * AN;
        __syncthreads();
#pragma unroll
        for (int i = 0; i < 16; i++) {
            int e = tid + i * 256;
            int rr2 = e >> 7, d = e & 127;
            Ks[rr2 * QSTR + d] = Kg[(size_t)(k0 + rr2) * HDD + d];
            Vs[rr2 * HDD + d]  = Vg[(size_t)(k0 + rr2) * HDD + d];
        }
        __syncthreads();

        float s[4];
#pragma unroll
        for (int j = 0; j < 4; j++) {
            int c = g + 8 * j;
            const float4* qp = reinterpret_cast<const float4*>(Qs + r * QSTR);
            const float4* kp = reinterpret_cast<const float4*>(Ks + c * QSTR);
            float a = 0.f;
#pragma unroll
            for (int k4 = 0; k4 < 32; k4++) {
                float4 qa = qp[k4], ka = kp[k4];
                a += qa.x * ka.x + qa.y * ka.y + qa.z * ka.z + qa.w * ka.w;
            }
            if (k0 + c > q0 + r) a = -1e30f;
            s[j] = a;
        }
        float mx = fmaxf(fmaxf(s[0], s[1]), fmaxf(s[2], s[3]));
        mx = fmaxf(mx, __shfl_xor_sync(~0u, mx, 1));
        mx = fmaxf(mx, __shfl_xor_sync(~0u, mx, 2));
        mx = fmaxf(mx, __shfl_xor_sync(~0u, mx, 4));
        float m_new = fmaxf(m_r, mx);
        float p[4];
        float psum = 0.f;
#pragma unroll
        for (int j = 0; j < 4; j++) { p[j] = __expf(s[j] - m_new); psum += p[j]; }
        psum += __shfl_xor_sync(~0u, psum, 1);
        psum += __shfl_xor_sync(~0u, psum, 2);
        psum += __shfl_xor_sync(~0u, psum, 4);
        float alpha = __expf(m_r - m_new);
        m_r = m_new;
        l_r = l_r * alpha + psum;
#pragma unroll
        for (int t = 0; t < 16; t++) acc[t] *= alpha;

        const int lanebase = (r & 3) * 8;
#pragma unroll
        for (int c = 0; c < AN; c++) {
            float pv = __shfl_sync(~0u, p[c >> 3], lanebase + (c & 7), 32);
            const float4* vp = reinterpret_cast<const float4*>(Vs + c * HDD + d0);
#pragma unroll
            for (int t4 = 0; t4 < 4; t4++) {
                float4 va = vp[t4];
                acc[t4 * 4 + 0] = fmaf(pv, va.x, acc[t4 * 4 + 0]);
                acc[t4 * 4 + 1] = fmaf(pv, va.y, acc[t4 * 4 + 1]);
                acc[t4 * 4 + 2] = fmaf(pv, va.z, acc[t4 * 4 + 2]);
                acc[t4 * 4 + 3] = fmaf(pv, va.w, acc[t4 * 4 + 3]);
            }
        }
    }

    float inv_l = 1.f / l_r;
    float* Og = g_ao + ((size_t)(b * LL + q0 + r) * HH + h) * HDD + d0;
#pragma unroll
    for (int t4 = 0; t4 < 4; t4++) {
        float4 v;
        v.x = acc[t4 * 4 + 0] * inv_l; v.y = acc[t4 * 4 + 1] * inv_l;
        v.z = acc[t4 * 4 + 2] * inv_l; v.w = acc[t4 * 4 + 3] * inv_l;
        reinterpret_cast<float4*>(Og)[t4] = v;
    }
}

// ---------------- router: logits, softmax, top-8, normalized dense weights ---
__global__ __launch_bounds__(128) void router_kernel(const float* __restrict__ rw)
{
    int n = blockIdx.x;
    const float* row = g_hm + (size_t)n * DMD;
    int w = threadIdx.x >> 5, lane = threadIdx.x & 31;
    __shared__ float logits[EE];
#pragma unroll
    for (int eb = 0; eb < 4; eb++) {
        int e = eb * 4 + w;
        const float* wr = rw + (size_t)e * DMD;
        float p = 0.f;
        for (int d = lane; d < DMD; d += 32) p += row[d] * wr[d];
#pragma unroll
        for (int o = 16; o > 0; o >>= 1) p += __shfl_xor_sync(~0u, p, o);
        if (lane == 0) logits[e] = p;
    }
    __syncthreads();
    if (threadIdx.x == 0) {
        float mx = -1e30f;
        for (int e = 0; e < EE; e++) mx = fmaxf(mx, logits[e]);
        float pr[EE];
        for (int e = 0; e < EE; e++) pr[e] = __expf(logits[e] - mx);
        bool used[EE];
        float wsel[EE];
        for (int e = 0; e < EE; e++) { used[e] = false; wsel[e] = 0.f; }
        float ssum = 0.f;
        for (int t = 0; t < TOPKK; t++) {
            float best = -1.f; int bi = 0;
            for (int e = 0; e < EE; e++)
                if (!used[e] && pr[e] > best) { best = pr[e]; bi = e; }
            used[bi] = true; wsel[bi] = best; ssum += best;
        }
        float inv = 1.f / ssum;
        for (int e = 0; e < EE; e++)
            g_wd[(size_t)n * EE + e] = used[e] ? wsel[e] * inv : 0.f;
    }
}

// -----------------------------------------------------------------------------
extern "C" void kernel_launch(void* const* d_in, const int* in_sizes, int n_in,
                              void* d_out, int out_size)
{
    const float* x    = (const float*)d_in[0];
    const float* cosb = (const float*)d_in[1];
    const float* sinb = (const float*)d_in[2];
    const float* naw  = (const float*)d_in[3];
    const float* q_w  = (const float*)d_in[4];
    const float* k_w  = (const float*)d_in[5];
    const float* v_w  = (const float*)d_in[6];
    const float* qn_w = (const float*)d_in[7];
    const float* kn_w = (const float*)d_in[8];
    const float* o_w  = (const float*)d_in[9];
    const float* nmw  = (const float*)d_in[10];
    const float* rw   = (const float*)d_in[11];
    const float* egw  = (const float*)d_in[12];
    const float* euw  = (const float*)d_in[13];
    const float* edw  = (const float*)d_in[14];
    float* out = (float*)d_out;

    // Resolve scratch addresses once; these driver calls are host-side only
    // and legal pre-capture, but caching keeps replays launch-only.
    static float *ph = nullptr, *pq, *pk, *pv, *pao, *phm, *pwd, *pact;
    static bool init_done = false;
    if (!init_done) {
        cudaGetSymbolAddress((void**)&ph,   g_h);
        cudaGetSymbolAddress((void**)&pq,   g_q);
        cudaGetSymbolAddress((void**)&pk,   g_k);
        cudaGetSymbolAddress((void**)&pv,   g_v);
        cudaGetSymbolAddress((void**)&pao,  g_ao);
        cudaGetSymbolAddress((void**)&phm,  g_hm);
        cudaGetSymbolAddress((void**)&pwd,  g_wd);
        cudaGetSymbolAddress((void**)&pact, g_actall);
        cudaFuncSetAttribute(attn_kernel,
                             cudaFuncAttributeMaxDynamicSharedMemorySize, ATTN_SMEM);
        init_done = true;
    }

    // 1) pre-attn norm
    rmsnorm_kernel<<<NTOK, 256>>>(x, naw, ph);

    // 2) QKV projections
    sgemm_bt<<<dim3(HH * HDD / 64, NTOK / 64), 256>>>(ph, q_w, pq, NTOK, HH * HDD, DMD, 0, nullptr);
    sgemm_bt<<<dim3(KVH * HDD / 64, NTOK / 64), 256>>>(ph, k_w, pk, NTOK, KVH * HDD, DMD, 0, nullptr);
    sgemm_bt<<<dim3(KVH * HDD / 64, NTOK / 64), 256>>>(ph, v_w, pv, NTOK, KVH * HDD, DMD, 0, nullptr);

    // 3) per-head norm + RoPE + transpose
    qkv_post<<<dim3(HH + 2 * KVH, LL, BB), 128>>>(cosb, sinb, qn_w, kn_w);

    // 4) causal flash attention
    attn_kernel<<<dim3(LL / AM, HH, BB), 256, ATTN_SMEM>>>();

    // 5) O projection + residual (writes x + attn into d_out)
    sgemm_bt<<<dim3(DMD / 64, NTOK / 64), 256>>>(pao, o_w, out, NTOK, DMD, HH * HDD, 1, x);

    // 6) pre-MLP norm
    rmsnorm_kernel<<<NTOK, 256>>>(out, nmw, phm);

    // 7) router
    router_kernel<<<NTOK, 128>>>(rw);

    // 8) MoE: fused batched gate+up (router-weight applied in epilogue)
    moe_gateup<<<dim3(MII / 64, NTOK / 64, EE), 256>>>(phm, egw, euw, pact, pwd);

    // 9) MoE: single fused down-proj accumulating into d_out (K = 16*128)
    moe_down<<<dim3(DMD / 64, NTOK / 64), 256>>>(pact, edw, out);
}

// round 5
// speedup vs baseline: 1.3128x; 1.3128x over previous
#include <cuda_runtime.h>
#include <cstdint>

#define BB   4
#define LL   1024
#define DMD  2048
#define HH   32
#define KVH  4
#define HDD  128
#define GG   (HH / KVH)
#define EE   16
#define TOPKK 8
#define MII  128
#define NTOK (BB * LL)
#define EPSF 1e-6f

// tf32 GEMM tiling
#define BM 128
#define BN 64
#define BK2 16
#define ASTR 20   // smem row stride (fp32 words): 20*r mod 32 hits all banks

// ---------------- scratch (device globals; no allocation allowed) ------------
__device__ float g_h  [NTOK * DMD];
__device__ float g_q  [NTOK * HH  * HDD];
__device__ float g_k  [NTOK * KVH * HDD];
__device__ float g_v  [NTOK * KVH * HDD];
__device__ float g_qt [NTOK * HH  * HDD];
__device__ float g_kt [NTOK * KVH * HDD];
__device__ float g_vt [NTOK * KVH * HDD];
__device__ float g_ao [NTOK * HH  * HDD];
__device__ float g_hm [NTOK * DMD];
__device__ float g_wd [NTOK * EE];
__device__ float g_actall[NTOK * EE * MII];  // [row][e*128+k]

// ---------------- tf32 helpers ----------------------------------------------
__device__ __forceinline__ uint32_t f2tf(float x) {
    uint32_t r; asm("cvt.rna.tf32.f32 %0, %1;" : "=r"(r) : "f"(x)); return r;
}
__device__ __forceinline__ void mma8(float* c, const uint32_t* a, const uint32_t* b) {
    asm volatile(
        "mma.sync.aligned.m16n8k8.row.col.f32.tf32.tf32.f32 "
        "{%0,%1,%2,%3}, {%4,%5,%6,%7}, {%8,%9}, {%0,%1,%2,%3};\n"
        : "+f"(c[0]), "+f"(c[1]), "+f"(c[2]), "+f"(c[3])
        : "r"(a[0]), "r"(a[1]), "r"(a[2]), "r"(a[3]), "r"(b[0]), "r"(b[1]));
}
// load 16 consecutive floats, cvt to tf32, store to smem (uint2 stores)
__device__ __forceinline__ void stage16(const float* g, uint32_t* s) {
    float4 v0 = *(const float4*)(g);
    float4 v1 = *(const float4*)(g + 4);
    float4 v2 = *(const float4*)(g + 8);
    float4 v3 = *(const float4*)(g + 12);
    *(uint2*)(s + 0)  = make_uint2(f2tf(v0.x), f2tf(v0.y));
    *(uint2*)(s + 2)  = make_uint2(f2tf(v0.z), f2tf(v0.w));
    *(uint2*)(s + 4)  = make_uint2(f2tf(v1.x), f2tf(v1.y));
    *(uint2*)(s + 6)  = make_uint2(f2tf(v1.z), f2tf(v1.w));
    *(uint2*)(s + 8)  = make_uint2(f2tf(v2.x), f2tf(v2.y));
    *(uint2*)(s + 10) = make_uint2(f2tf(v2.z), f2tf(v2.w));
    *(uint2*)(s + 12) = make_uint2(f2tf(v3.x), f2tf(v3.y));
    *(uint2*)(s + 14) = make_uint2(f2tf(v3.z), f2tf(v3.w));
}
__device__ __forceinline__ void stage8(const float* g, uint32_t* s) {
    float4 v0 = *(const float4*)(g);
    float4 v1 = *(const float4*)(g + 4);
    *(uint2*)(s + 0) = make_uint2(f2tf(v0.x), f2tf(v0.y));
    *(uint2*)(s + 2) = make_uint2(f2tf(v0.z), f2tf(v0.w));
    *(uint2*)(s + 4) = make_uint2(f2tf(v1.x), f2tf(v1.y));
    *(uint2*)(s + 6) = make_uint2(f2tf(v1.z), f2tf(v1.w));
}

// ---------------- tf32 GEMM: C = A(MxK) @ B(NxK)^T ---------------------------
// MODE 0: C = acc        MODE 1: C = aux + acc        MODE 4: C += acc, B blocked
// MODE 4 B layout: B(n, k) = Dw[e][n][koff], e = k>>7, koff = k&127 (down proj)
template<int MODE>
__global__ __launch_bounds__(128) void gemm_tf32(
    const float* __restrict__ A, const float* __restrict__ B,
    float* __restrict__ C, const float* __restrict__ aux, int N, int K)
{
    __shared__ uint32_t As[2][BM * ASTR];
    __shared__ uint32_t Bs[2][BN * ASTR];
    const int tid  = threadIdx.x;
    const int row0 = blockIdx.y * BM;
    const int col0 = blockIdx.x * BN;
    const int warp = tid >> 5, lane = tid & 31;
    const int wr = (warp >> 1) * 64, wc = (warp & 1) * 32;
    const int lr = lane >> 2, lc = lane & 3;
    const int brow = tid & 63, bh = (tid >> 6) * 8;

    const float* Ag = A + (size_t)(row0 + tid) * K;

    float acc[4][4][4] = {};

    // stage chunk 0
    stage16(Ag, &As[0][tid * ASTR]);
    {
        const float* bg = (MODE == 4)
            ? B + (size_t)(col0 + brow) * MII + bh
            : B + (size_t)(col0 + brow) * K + bh;
        stage8(bg, &Bs[0][brow * ASTR + bh]);
    }
    __syncthreads();

    const int nchunk = K / BK2;
    for (int c = 0; c < nchunk; c++) {
        int buf = c & 1;
        if (c + 1 < nchunk) {
            int k0 = (c + 1) * BK2;
            stage16(Ag + k0, &As[buf ^ 1][tid * ASTR]);
            const float* bg = (MODE == 4)
                ? B + (size_t)(k0 >> 7) * ((size_t)DMD * MII)
                    + (size_t)(col0 + brow) * MII + (k0 & 127) + bh
                : B + (size_t)(col0 + brow) * K + k0 + bh;
            stage8(bg, &Bs[buf ^ 1][brow * ASTR + bh]);
        }
        const uint32_t* sA = As[buf];
        const uint32_t* sB = Bs[buf];
#pragma unroll
        for (int ks = 0; ks < 2; ks++) {
            uint32_t af[4][4], bf[4][2];
#pragma unroll
            for (int mi = 0; mi < 4; mi++) {
                const uint32_t* p = sA + (wr + mi * 16 + lr) * ASTR + ks * 8 + lc;
                af[mi][0] = p[0];
                af[mi][1] = p[8 * ASTR];
                af[mi][2] = p[4];
                af[mi][3] = p[8 * ASTR + 4];
            }
#pragma unroll
            for (int ni = 0; ni < 4; ni++) {
                const uint32_t* p = sB + (wc + ni * 8 + lr) * ASTR + ks * 8 + lc;
                bf[ni][0] = p[0];
                bf[ni][1] = p[4];
            }
#pragma unroll
            for (int mi = 0; mi < 4; mi++)
#pragma unroll
                for (int ni = 0; ni < 4; ni++)
                    mma8(acc[mi][ni], af[mi], bf[ni]);
        }
        __syncthreads();
    }

#pragma unroll
    for (int mi = 0; mi < 4; mi++) {
        int r = row0 + wr + mi * 16 + lr;
#pragma unroll
        for (int ni = 0; ni < 4; ni++) {
            int cc = col0 + wc + ni * 8 + lc * 2;
            size_t i0 = (size_t)r * N + cc;
            size_t i1 = i0 + (size_t)8 * N;
            float2 v0 = make_float2(acc[mi][ni][0], acc[mi][ni][1]);
            float2 v1 = make_float2(acc[mi][ni][2], acc[mi][ni][3]);
            if (MODE == 1) {
                float2 a0 = *(const float2*)(aux + i0);
                float2 a1 = *(const float2*)(aux + i1);
                v0.x += a0.x; v0.y += a0.y; v1.x += a1.x; v1.y += a1.y;
            }
            if (MODE == 4) {
                float2 a0 = *(const float2*)(C + i0);
                float2 a1 = *(const float2*)(C + i1);
                v0.x += a0.x; v0.y += a0.y; v1.x += a1.x; v1.y += a1.y;
            }
            *(float2*)(C + i0) = v0;
            *(float2*)(C + i1) = v1;
        }
    }
}

// -------- MoE fused gate+up (tf32): act = w(row,e)*silu(g)*u -----------------
__global__ __launch_bounds__(128) void moe_gateup_tf32(
    const float* __restrict__ A, const float* __restrict__ Gw,
    const float* __restrict__ Uw, float* __restrict__ Act,
    const float* __restrict__ wd)
{
    __shared__ uint32_t As[2][BM * ASTR];
    __shared__ uint32_t Gs[2][BN * ASTR];
    __shared__ uint32_t Us[2][BN * ASTR];
    const int e    = blockIdx.z;
    const int tid  = threadIdx.x;
    const int row0 = blockIdx.y * BM;
    const int col0 = blockIdx.x * BN;   // within-expert col (0 or 64)
    const int warp = tid >> 5, lane = tid & 31;
    const int wr = (warp >> 1) * 64, wc = (warp & 1) * 32;
    const int lr = lane >> 2, lc = lane & 3;
    const int brow = tid & 63, bh = (tid >> 6) * 8;

    const float* Ag = A  + (size_t)(row0 + tid) * DMD;
    const float* Gg = Gw + (size_t)e * MII * DMD + (size_t)(col0 + brow) * DMD + bh;
    const float* Ug = Uw + (size_t)e * MII * DMD + (size_t)(col0 + brow) * DMD + bh;

    float accg[4][4][4] = {};
    float accu[4][4][4] = {};

    stage16(Ag, &As[0][tid * ASTR]);
    stage8(Gg, &Gs[0][brow * ASTR + bh]);
    stage8(Ug, &Us[0][brow * ASTR + bh]);
    __syncthreads();

    const int nchunk = DMD / BK2;
    for (int c = 0; c < nchunk; c++) {
        int buf = c & 1;
        if (c + 1 < nchunk) {
            int k0 = (c + 1) * BK2;
            stage16(Ag + k0, &As[buf ^ 1][tid * ASTR]);
            stage8(Gg + k0, &Gs[buf ^ 1][brow * ASTR + bh]);
            stage8(Ug + k0, &Us[buf ^ 1][brow * ASTR + bh]);
        }
        const uint32_t* sA = As[buf];
        const uint32_t* sG = Gs[buf];
        const uint32_t* sU = Us[buf];
#pragma unroll
        for (int ks = 0; ks < 2; ks++) {
            uint32_t af[4][4], gf[4][2], uf[4][2];
#pragma unroll
            for (int mi = 0; mi < 4; mi++) {
                const uint32_t* p = sA + (wr + mi * 16 + lr) * ASTR + ks * 8 + lc;
                af[mi][0] = p[0];
                af[mi][1] = p[8 * ASTR];
                af[mi][2] = p[4];
                af[mi][3] = p[8 * ASTR + 4];
            }
#pragma unroll
            for (int ni = 0; ni < 4; ni++) {
                int off = (wc + ni * 8 + lr) * ASTR + ks * 8 + lc;
                gf[ni][0] = sG[off];     gf[ni][1] = sG[off + 4];
                uf[ni][0] = sU[off];     uf[ni][1] = sU[off + 4];
            }
#pragma unroll
            for (int mi = 0; mi < 4; mi++)
#pragma unroll
                for (int ni = 0; ni < 4; ni++) {
                    mma8(accg[mi][ni], af[mi], gf[ni]);
                    mma8(accu[mi][ni], af[mi], uf[ni]);
                }
        }
        __syncthreads();
    }

#pragma unroll
    for (int mi = 0; mi < 4; mi++) {
        int r = row0 + wr + mi * 16 + lr;
        float w0 = wd[(size_t)r * EE + e];
        float w1 = wd[(size_t)(r + 8) * EE + e];
#pragma unroll
        for (int ni = 0; ni < 4; ni++) {
            int cc = col0 + wc + ni * 8 + lc * 2;
            size_t i0 = (size_t)r * (EE * MII) + e * MII + cc;
            size_t i1 = i0 + (size_t)8 * (EE * MII);
            float g0 = accg[mi][ni][0], g1 = accg[mi][ni][1];
            float g2 = accg[mi][ni][2], g3 = accg[mi][ni][3];
            float2 v0, v1;
            v0.x = w0 * (g0 / (1.f + __expf(-g0))) * accu[mi][ni][0];
            v0.y = w0 * (g1 / (1.f + __expf(-g1))) * accu[mi][ni][1];
            v1.x = w1 * (g2 / (1.f + __expf(-g2))) * accu[mi][ni][2];
            v1.y = w1 * (g3 / (1.f + __expf(-g3))) * accu[mi][ni][3];
            *(float2*)(Act + i0) = v0;
            *(float2*)(Act + i1) = v1;
        }
    }
}

// ---------------- row RMSNorm over DM ----------------------------------------
__global__ __launch_bounds__(256) void rmsnorm_kernel(
    const float* __restrict__ x, const float* __restrict__ w, float* __restrict__ y)
{
    int row = blockIdx.x;
    const float* xr = x + (size_t)row * DMD;
    float ss = 0.f;
    for (int d = threadIdx.x; d < DMD; d += 256) { float v = xr[d]; ss += v * v; }
    __shared__ float red[8];
#pragma unroll
    for (int o = 16; o > 0; o >>= 1) ss += __shfl_xor_sync(~0u, ss, o);
    if ((threadIdx.x & 31) == 0) red[threadIdx.x >> 5] = ss;
    __syncthreads();
    if (threadIdx.x < 8) {
        float t = red[threadIdx.x];
#pragma unroll
        for (int o = 4; o > 0; o >>= 1) t += __shfl_xor_sync(0xffu, t, o);
        if (threadIdx.x == 0) red[0] = t;
    }
    __syncthreads();
    float scale = rsqrtf(red[0] / (float)DMD + EPSF);
    for (int d = threadIdx.x; d < DMD; d += 256)
        y[(size_t)row * DMD + d] = xr[d] * scale * w[d];
}

// -------- per-head RMSNorm + RoPE + transpose to (b,head,l,d); V transpose ---
__global__ __launch_bounds__(128) void qkv_post(
    const float* __restrict__ cosb, const float* __restrict__ sinb,
    const float* __restrict__ qn_w, const float* __restrict__ kn_w)
{
    int b = blockIdx.z, l = blockIdx.y, rr = blockIdx.x;
    int d = threadIdx.x;
    int n = b * LL + l;
    __shared__ float buf[HDD];
    __shared__ float red[4];

    const float* src; float* dst; const float* nw;
    if (rr < HH) {
        src = g_q + (size_t)n * HH * HDD + rr * HDD;
        dst = g_qt + ((size_t)(b * HH + rr) * LL + l) * HDD;
        nw = qn_w;
    } else if (rr < HH + KVH) {
        int kv = rr - HH;
        src = g_k + (size_t)n * KVH * HDD + kv * HDD;
        dst = g_kt + ((size_t)(b * KVH + kv) * LL + l) * HDD;
        nw = kn_w;
    } else {
        int kv = rr - HH - KVH;
        g_vt[((size_t)(b * KVH + kv) * LL + l) * HDD + d] =
            g_v[(size_t)n * KVH * HDD + kv * HDD + d];
        return;
    }
    float v = src[d];
    float ss = v * v;
#pragma unroll
    for (int o = 16; o > 0; o >>= 1) ss += __shfl_xor_sync(~0u, ss, o);
    if ((d & 31) == 0) red[d >> 5] = ss;
    __syncthreads();
    float tot = red[0] + red[1] + red[2] + red[3];
    float nv = v * rsqrtf(tot / (float)HDD + EPSF) * nw[d];
    buf[d] = nv;
    __syncthreads();
    float other = (d < HDD / 2) ? -buf[d + HDD / 2] : buf[d - HDD / 2];
    float c = cosb[(size_t)n * HDD + d];
    float s = sinb[(size_t)n * HDD + d];
    dst[d] = c * nv + s * other;
}

// ---------------- fp32 flash attention (causal, GQA) -------------------------
#define AM 32
#define AN 32
#define QSTR 132
#define ATTN_SMEM ((AM * QSTR + AN * QSTR + AN * HDD) * 4)

__global__ __launch_bounds__(256) void attn_kernel()
{
    extern __shared__ float sm[];
    float* Qs = sm;
    float* Ks = Qs + AM * QSTR;
    float* Vs = Ks + AN * QSTR;

    const int tid = threadIdx.x;
    const int b = blockIdx.z, h = blockIdx.y;
    const int q0 = blockIdx.x * AM;
    const int kv = h / GG;
    const float SCALE = 0.08838834764831845f;

    const float* Qg = g_qt + ((size_t)(b * HH + h) * LL + q0) * HDD;
    const float* Kg = g_kt + ((size_t)(b * KVH + kv) * LL) * HDD;
    const float* Vg = g_vt + ((size_t)(b * KVH + kv) * LL) * HDD;

#pragma unroll
    for (int i = 0; i < 16; i++) {
        int e = tid + i * 256;
        int r = e >> 7, d = e & 127;
        Qs[r * QSTR + d] = Qg[(size_t)r * HDD + d] * SCALE;
    }

    const int r = tid >> 3;
    const int g = tid & 7;
    const int d0 = g * 16;

    float m_r = -1e30f, l_r = 0.f;
    float acc[16];
#pragma unroll
    for (int t = 0; t < 16; t++) acc[t] = 0.f;

    const int ntile = q0 / AN + 1;
    for (int kt = 0; kt < ntile; kt++) {
        int k0 = kt * AN;
        __syncthreads();
#pragma unroll
        for (int i = 0; i < 16; i++) {
            int e = tid + i * 256;
            int rr2 = e >> 7, d = e & 127;
            Ks[rr2 * QSTR + d] = Kg[(size_t)(k0 + rr2) * HDD + d];
            Vs[rr2 * HDD + d]  = Vg[(size_t)(k0 + rr2) * HDD + d];
        }
        __syncthreads();

        float s[4];
#pragma unroll
        for (int j = 0; j < 4; j++) {
            int c = g + 8 * j;
            const float4* qp = reinterpret_cast<const float4*>(Qs + r * QSTR);
            const float4* kp = reinterpret_cast<const float4*>(Ks + c * QSTR);
            float a = 0.f;
#pragma unroll
            for (int k4 = 0; k4 < 32; k4++) {
                float4 qa = qp[k4], ka = kp[k4];
                a += qa.x * ka.x + qa.y * ka.y + qa.z * ka.z + qa.w * ka.w;
            }
            if (k0 + c > q0 + r) a = -1e30f;
            s[j] = a;
        }
        float mx = fmaxf(fmaxf(s[0], s[1]), fmaxf(s[2], s[3]));
        mx = fmaxf(mx, __shfl_xor_sync(~0u, mx, 1));
        mx = fmaxf(mx, __shfl_xor_sync(~0u, mx, 2));
        mx = fmaxf(mx, __shfl_xor_sync(~0u, mx, 4));
        float m_new = fmaxf(m_r, mx);
        float p[4];
        float psum = 0.f;
#pragma unroll
        for (int j = 0; j < 4; j++) { p[j] = __expf(s[j] - m_new); psum += p[j]; }
        psum += __shfl_xor_sync(~0u, psum, 1);
        psum += __shfl_xor_sync(~0u, psum, 2);
        psum += __shfl_xor_sync(~0u, psum, 4);
        float alpha = __expf(m_r - m_new);
        m_r = m_new;
        l_r = l_r * alpha + psum;
#pragma unroll
        for (int t = 0; t < 16; t++) acc[t] *= alpha;

        const int lanebase = (r & 3) * 8;
#pragma unroll
        for (int c = 0; c < AN; c++) {
            float pv = __shfl_sync(~0u, p[c >> 3], lanebase + (c & 7), 32);
            const float4* vp = reinterpret_cast<const float4*>(Vs + c * HDD + d0);
#pragma unroll
            for (int t4 = 0; t4 < 4; t4++) {
                float4 va = vp[t4];
                acc[t4 * 4 + 0] = fmaf(pv, va.x, acc[t4 * 4 + 0]);
                acc[t4 * 4 + 1] = fmaf(pv, va.y, acc[t4 * 4 + 1]);
                acc[t4 * 4 + 2] = fmaf(pv, va.z, acc[t4 * 4 + 2]);
                acc[t4 * 4 + 3] = fmaf(pv, va.w, acc[t4 * 4 + 3]);
            }
        }
    }

    float inv_l = 1.f / l_r;
    float* Og = g_ao + ((size_t)(b * LL + q0 + r) * HH + h) * HDD + d0;
#pragma unroll
    for (int t4 = 0; t4 < 4; t4++) {
        float4 v;
        v.x = acc[t4 * 4 + 0] * inv_l; v.y = acc[t4 * 4 + 1] * inv_l;
        v.z = acc[t4 * 4 + 2] * inv_l; v.w = acc[t4 * 4 + 3] * inv_l;
        reinterpret_cast<float4*>(Og)[t4] = v;
    }
}

// ---------------- router ------------------------------------------------------
__global__ __launch_bounds__(128) void router_kernel(const float* __restrict__ rw)
{
    int n = blockIdx.x;
    const float* row = g_hm + (size_t)n * DMD;
    int w = threadIdx.x >> 5, lane = threadIdx.x & 31;
    __shared__ float logits[EE];
#pragma unroll
    for (int eb = 0; eb < 4; eb++) {
        int e = eb * 4 + w;
        const float* wr = rw + (size_t)e * DMD;
        float p = 0.f;
        for (int d = lane; d < DMD; d += 32) p += row[d] * wr[d];
#pragma unroll
        for (int o = 16; o > 0; o >>= 1) p += __shfl_xor_sync(~0u, p, o);
        if (lane == 0) logits[e] = p;
    }
    __syncthreads();
    if (threadIdx.x == 0) {
        float mx = -1e30f;
        for (int e = 0; e < EE; e++) mx = fmaxf(mx, logits[e]);
        float pr[EE];
        for (int e = 0; e < EE; e++) pr[e] = __expf(logits[e] - mx);
        bool used[EE];
        float wsel[EE];
        for (int e = 0; e < EE; e++) { used[e] = false; wsel[e] = 0.f; }
        float ssum = 0.f;
        for (int t = 0; t < TOPKK; t++) {
            float best = -1.f; int bi = 0;
            for (int e = 0; e < EE; e++)
                if (!used[e] && pr[e] > best) { best = pr[e]; bi = e; }
            used[bi] = true; wsel[bi] = best; ssum += best;
        }
        float inv = 1.f / ssum;
        for (int e = 0; e < EE; e++)
            g_wd[(size_t)n * EE + e] = used[e] ? wsel[e] * inv : 0.f;
    }
}

// -----------------------------------------------------------------------------
extern "C" void kernel_launch(void* const* d_in, const int* in_sizes, int n_in,
                              void* d_out, int out_size)
{
    const float* x    = (const float*)d_in[0];
    const float* cosb = (const float*)d_in[1];
    const float* sinb = (const float*)d_in[2];
    const float* naw  = (const float*)d_in[3];
    const float* q_w  = (const float*)d_in[4];
    const float* k_w  = (const float*)d_in[5];
    const float* v_w  = (const float*)d_in[6];
    const float* qn_w = (const float*)d_in[7];
    const float* kn_w = (const float*)d_in[8];
    const float* o_w  = (const float*)d_in[9];
    const float* nmw  = (const float*)d_in[10];
    const float* rw   = (const float*)d_in[11];
    const float* egw  = (const float*)d_in[12];
    const float* euw  = (const float*)d_in[13];
    const float* edw  = (const float*)d_in[14];
    float* out = (float*)d_out;

    static float *ph = nullptr, *pq, *pk, *pv, *pao, *phm, *pwd, *pact;
    static bool init_done = false;
    if (!init_done) {
        cudaGetSymbolAddress((void**)&ph,   g_h);
        cudaGetSymbolAddress((void**)&pq,   g_q);
        cudaGetSymbolAddress((void**)&pk,   g_k);
        cudaGetSymbolAddress((void**)&pv,   g_v);
        cudaGetSymbolAddress((void**)&pao,  g_ao);
        cudaGetSymbolAddress((void**)&phm,  g_hm);
        cudaGetSymbolAddress((void**)&pwd,  g_wd);
        cudaGetSymbolAddress((void**)&pact, g_actall);
        cudaFuncSetAttribute(attn_kernel,
                             cudaFuncAttributeMaxDynamicSharedMemorySize, ATTN_SMEM);
        init_done = true;
    }

    // 1) pre-attn norm
    rmsnorm_kernel<<<NTOK, 256>>>(x, naw, ph);

    // 2) QKV projections (tf32 tensor core)
    gemm_tf32<0><<<dim3(HH * HDD / BN, NTOK / BM), 128>>>(ph, q_w, pq, nullptr, HH * HDD, DMD);
    gemm_tf32<0><<<dim3(KVH * HDD / BN, NTOK / BM), 128>>>(ph, k_w, pk, nullptr, KVH * HDD, DMD);
    gemm_tf32<0><<<dim3(KVH * HDD / BN, NTOK / BM), 128>>>(ph, v_w, pv, nullptr, KVH * HDD, DMD);

    // 3) per-head norm + RoPE + transpose
    qkv_post<<<dim3(HH + 2 * KVH, LL, BB), 128>>>(cosb, sinb, qn_w, kn_w);

    // 4) causal flash attention (fp32)
    attn_kernel<<<dim3(LL / AM, HH, BB), 256, ATTN_SMEM>>>();

    // 5) O projection + residual
    gemm_tf32<1><<<dim3(DMD / BN, NTOK / BM), 128>>>(pao, o_w, out, x, DMD, HH * HDD);

    // 6) pre-MLP norm
    rmsnorm_kernel<<<NTOK, 256>>>(out, nmw, phm);

    // 7) router (fp32)
    router_kernel<<<NTOK, 128>>>(rw);

    // 8) MoE fused gate+up (tf32), router weight in epilogue
    moe_gateup_tf32<<<dim3(MII / BN, NTOK / BM, EE), 128>>>(phm, egw, euw, pact, pwd);

    // 9) MoE down proj: out += act @ dw^T over K = 16*128 (tf32)
    gemm_tf32<4><<<dim3(DMD / BN, NTOK / BM), 128>>>(pact, edw, out, nullptr, DMD, EE * MII);
}

// round 7
// speedup vs baseline: 1.5849x; 1.2072x over previous
#include <cuda_runtime.h>
#include <cstdint>

#define BB   4
#define LL   1024
#define DMD  2048
#define HH   32
#define KVH  4
#define HDD  128
#define GG   (HH / KVH)
#define EE   16
#define TOPKK 8
#define MII  128
#define NTOK (BB * LL)
#define EPSF 1e-6f
#define NQKV (HH * HDD + 2 * KVH * HDD)   // 5120

// GEMM tiling
#define BM 128
#define BN 128
#define BK 16
#define ASTR 20      // smem row stride in floats; 20*r mod 32 covers all banks
#define NSTAGE 3
#define GEMM_SMEM (NSTAGE * (BM + BN) * ASTR * 4)   // 61440 bytes

// ---------------- scratch (device globals; no allocation allowed) ------------
__device__ float g_h   [NTOK * DMD];
__device__ float g_wqkv[NQKV * DMD];        // concat(q_w, k_w, v_w)
__device__ float g_qkv [NTOK * NQKV];       // token-major qkv proj
__device__ float g_qt  [NTOK * HH  * HDD];  // (b,h,l,d)
__device__ float g_kt  [NTOK * KVH * HDD];
__device__ float g_vt  [NTOK * KVH * HDD];
__device__ float g_ao  [NTOK * HH  * HDD];
__device__ float g_hm  [NTOK * DMD];
__device__ float g_wd  [NTOK * EE];
__device__ float g_gate[NTOK * EE * MII];
__device__ float g_up  [NTOK * EE * MII];
__device__ float g_act [NTOK * EE * MII];

// ---------------- helpers ----------------------------------------------------
__device__ __forceinline__ uint32_t s2u(const void* p) {
    return (uint32_t)__cvta_generic_to_shared(p);
}
__device__ __forceinline__ void cp16(uint32_t s, const void* g) {
    asm volatile("cp.async.cg.shared.global [%0], [%1], 16;\n" :: "r"(s), "l"(g));
}
__device__ __forceinline__ void cp_commit() {
    asm volatile("cp.async.commit_group;\n" ::: "memory");
}
__device__ __forceinline__ void cp_wait1() {
    asm volatile("cp.async.wait_group 1;\n" ::: "memory");
}
__device__ __forceinline__ void mma8(float* c, const uint32_t* a, const uint32_t* b) {
    asm volatile(
        "mma.sync.aligned.m16n8k8.row.col.f32.tf32.tf32.f32 "
        "{%0,%1,%2,%3}, {%4,%5,%6,%7}, {%8,%9}, {%0,%1,%2,%3};\n"
        : "+f"(c[0]), "+f"(c[1]), "+f"(c[2]), "+f"(c[3])
        : "r"(a[0]), "r"(a[1]), "r"(a[2]), "r"(a[3]), "r"(b[0]), "r"(b[1]));
}

// ---------------- tf32 cp.async GEMM: C = A(MxK) @ B(NxK)^T ------------------
// MODE 0: C = acc   MODE 1: C = aux + acc   MODE 4: C += acc, B expert-blocked
// MODE 4 B layout: B(n,k) = Dw[k>>7][n][k&127]
template<int MODE>
__global__ __launch_bounds__(256, 2) void gemm_ta(
    const float* __restrict__ A, const float* __restrict__ B,
    float* __restrict__ C, const float* __restrict__ aux, int N, int K)
{
    extern __shared__ float smem[];
    float* As = smem;                          // [NSTAGE][BM*ASTR]
    float* Bs = smem + NSTAGE * BM * ASTR;     // [NSTAGE][BN*ASTR]
    const int tid  = threadIdx.x;
    const int row0 = blockIdx.y * BM;
    const int col0 = blockIdx.x * BN;
    const int warp = tid >> 5, lane = tid & 31;
    const int wr = (warp >> 2) * 64, wc = (warp & 3) * 32;
    const int lr = lane >> 2, lc = lane & 3;
    const int ldrow = tid >> 1, ldoff = (tid & 1) * 8;

    const float* Agp = A + (size_t)(row0 + ldrow) * K + ldoff;
    const float* Bgp = B + (size_t)(col0 + ldrow) * K + ldoff;   // non-blocked

    float acc[4][4][4] = {};

#define ISSUE(cc) do {                                                         \
        int st_ = (cc) % NSTAGE; int k0_ = (cc) * BK;                          \
        uint32_t sa_ = s2u(&As[st_ * BM * ASTR + ldrow * ASTR + ldoff]);       \
        const float* ag_ = Agp + k0_;                                          \
        cp16(sa_, ag_); cp16(sa_ + 16, ag_ + 4);                               \
        const float* bg_ = (MODE == 4)                                         \
            ? B + (size_t)(k0_ >> 7) * ((size_t)DMD * MII)                     \
                + (size_t)(col0 + ldrow) * MII + (k0_ & 127) + ldoff           \
            : Bgp + k0_;                                                       \
        uint32_t sb_ = s2u(&Bs[st_ * BN * ASTR + ldrow * ASTR + ldoff]);       \
        cp16(sb_, bg_); cp16(sb_ + 16, bg_ + 4);                               \
    } while (0)

    ISSUE(0); cp_commit();
    ISSUE(1); cp_commit();

    const int nchunk = K / BK;
    for (int c = 0; c < nchunk; c++) {
        cp_wait1();
        __syncthreads();
        if (c + 2 < nchunk) ISSUE(c + 2);
        cp_commit();

        int st = c % NSTAGE;
        const uint32_t* sA = (const uint32_t*)(As + st * BM * ASTR);
        const uint32_t* sB = (const uint32_t*)(Bs + st * BN * ASTR);
#pragma unroll
        for (int ks = 0; ks < 2; ks++) {
            uint32_t af[4][4], bf[4][2];
#pragma unroll
            for (int mi = 0; mi < 4; mi++) {
                const uint32_t* p = sA + (wr + mi * 16 + lr) * ASTR + ks * 8 + lc;
                af[mi][0] = p[0];
                af[mi][1] = p[8 * ASTR];
                af[mi][2] = p[4];
                af[mi][3] = p[8 * ASTR + 4];
            }
#pragma unroll
            for (int ni = 0; ni < 4; ni++) {
                const uint32_t* p = sB + (wc + ni * 8 + lr) * ASTR + ks * 8 + lc;
                bf[ni][0] = p[0];
                bf[ni][1] = p[4];
            }
#pragma unroll
            for (int mi = 0; mi < 4; mi++)
#pragma unroll
                for (int ni = 0; ni < 4; ni++)
                    mma8(acc[mi][ni], af[mi], bf[ni]);
        }
    }
#undef ISSUE

#pragma unroll
    for (int mi = 0; mi < 4; mi++) {
        int r = row0 + wr + mi * 16 + lr;
#pragma unroll
        for (int ni = 0; ni < 4; ni++) {
            int cc = col0 + wc + ni * 8 + lc * 2;
            size_t i0 = (size_t)r * N + cc;
            size_t i1 = i0 + (size_t)8 * N;
            float2 v0 = make_float2(acc[mi][ni][0], acc[mi][ni][1]);
            float2 v1 = make_float2(acc[mi][ni][2], acc[mi][ni][3]);
            if (MODE == 1) {
                float2 a0 = *(const float2*)(aux + i0);
                float2 a1 = *(const float2*)(aux + i1);
                v0.x += a0.x; v0.y += a0.y; v1.x += a1.x; v1.y += a1.y;
            }
            if (MODE == 4) {
                float2 a0 = *(const float2*)(C + i0);
                float2 a1 = *(const float2*)(C + i1);
                v0.x += a0.x; v0.y += a0.y; v1.x += a1.x; v1.y += a1.y;
            }
            *(float2*)(C + i0) = v0;
            *(float2*)(C + i1) = v1;
        }
    }
}

// ---------------- MoE elementwise: act = wd * silu(gate) * up ----------------
__global__ __launch_bounds__(256) void moe_act_kernel()
{
    int n = blockIdx.x;
    const float4* gp = (const float4*)(g_gate + (size_t)n * EE * MII);
    const float4* up = (const float4*)(g_up   + (size_t)n * EE * MII);
    float4*       ap = (float4*)(g_act + (size_t)n * EE * MII);
    const float*  wdp = g_wd + (size_t)n * EE;
#pragma unroll
    for (int t = 0; t < 2; t++) {
        int i = threadIdx.x + t * 256;       // float4 index; col = i*4
        float w = wdp[(i * 4) >> 7];
        float4 g = gp[i], u = up[i], o;
        o.x = w * (g.x / (1.f + __expf(-g.x))) * u.x;
        o.y = w * (g.y / (1.f + __expf(-g.y))) * u.y;
        o.z = w * (g.z / (1.f + __expf(-g.z))) * u.z;
        o.w = w * (g.w / (1.f + __expf(-g.w))) * u.w;
        ap[i] = o;
    }
}

// ---------------- row RMSNorm over DM ----------------------------------------
__global__ __launch_bounds__(256) void rmsnorm_kernel(
    const float* __restrict__ x, const float* __restrict__ w, float* __restrict__ y)
{
    int row = blockIdx.x;
    const float* xr = x + (size_t)row * DMD;
    float ss = 0.f;
    for (int d = threadIdx.x; d < DMD; d += 256) { float v = xr[d]; ss += v * v; }
    __shared__ float red[8];
#pragma unroll
    for (int o = 16; o > 0; o >>= 1) ss += __shfl_xor_sync(~0u, ss, o);
    if ((threadIdx.x & 31) == 0) red[threadIdx.x >> 5] = ss;
    __syncthreads();
    if (threadIdx.x < 8) {
        float t = red[threadIdx.x];
#pragma unroll
        for (int o = 4; o > 0; o >>= 1) t += __shfl_xor_sync(0xffu, t, o);
        if (threadIdx.x == 0) red[0] = t;
    }
    __syncthreads();
    float scale = rsqrtf(red[0] / (float)DMD + EPSF);
    for (int d = threadIdx.x; d < DMD; d += 256)
        y[(size_t)row * DMD + d] = xr[d] * scale * w[d];
}

// -------- per-head RMSNorm + RoPE + transpose; V transpose -------------------
__global__ __launch_bounds__(128) void qkv_post(
    const float* __restrict__ cosb, const float* __restrict__ sinb,
    const float* __restrict__ qn_w, const float* __restrict__ kn_w)
{
    int b = blockIdx.z, l = blockIdx.y, rr = blockIdx.x;
    int d = threadIdx.x;
    int n = b * LL + l;
    __shared__ float buf[HDD];
    __shared__ float red[4];

    const float* src; float* dst; const float* nw;
    if (rr < HH) {
        src = g_qkv + (size_t)n * NQKV + rr * HDD;
        dst = g_qt + ((size_t)(b * HH + rr) * LL + l) * HDD;
        nw = qn_w;
    } else if (rr < HH + KVH) {
        int kv = rr - HH;
        src = g_qkv + (size_t)n * NQKV + HH * HDD + kv * HDD;
        dst = g_kt + ((size_t)(b * KVH + kv) * LL + l) * HDD;
        nw = kn_w;
    } else {
        int kv = rr - HH - KVH;
        g_vt[((size_t)(b * KVH + kv) * LL + l) * HDD + d] =
            g_qkv[(size_t)n * NQKV + (HH + KVH) * HDD + kv * HDD + d];
        return;
    }
    float v = src[d];
    float ss = v * v;
#pragma unroll
    for (int o = 16; o > 0; o >>= 1) ss += __shfl_xor_sync(~0u, ss, o);
    if ((d & 31) == 0) red[d >> 5] = ss;
    __syncthreads();
    float tot = red[0] + red[1] + red[2] + red[3];
    float nv = v * rsqrtf(tot / (float)HDD + EPSF) * nw[d];
    buf[d] = nv;
    __syncthreads();
    float other = (d < HDD / 2) ? -buf[d + HDD / 2] : buf[d - HDD / 2];
    float c = cosb[(size_t)n * HDD + d];
    float s = sinb[(size_t)n * HDD + d];
    dst[d] = c * nv + s * other;
}

// ---------------- fp32 flash attention (causal, GQA) -------------------------
#define AM 32
#define AN 32
#define QSTR 132
#define ATTN_SMEM ((AM * QSTR + AN * QSTR + AN * HDD) * 4)

__global__ __launch_bounds__(256) void attn_kernel()
{
    extern __shared__ float sm[];
    float* Qs = sm;
    float* Ks = Qs + AM * QSTR;
    float* Vs = Ks + AN * QSTR;

    const int tid = threadIdx.x;
    const int b = blockIdx.z, h = blockIdx.y;
    const int q0 = blockIdx.x * AM;
    const int kv = h / GG;
    const float SCALE = 0.08838834764831845f;

    const float* Qg = g_qt + ((size_t)(b * HH + h) * LL + q0) * HDD;
    const float* Kg = g_kt + ((size_t)(b * KVH + kv) * LL) * HDD;
    const float* Vg = g_vt + ((size_t)(b * KVH + kv) * LL) * HDD;

#pragma unroll
    for (int i = 0; i < 16; i++) {
        int e = tid + i * 256;
        int r = e >> 7, d = e & 127;
        Qs[r * QSTR + d] = Qg[(size_t)r * HDD + d] * SCALE;
    }

    const int r = tid >> 3;
    const int g = tid & 7;
    const int d0 = g * 16;

    float m_r = -1e30f, l_r = 0.f;
    float acc[16];
#pragma unroll
    for (int t = 0; t < 16; t++) acc[t] = 0.f;

    const int ntile = q0 / AN + 1;
    for (int kt = 0; kt < ntile; kt++) {
        int k0 = kt * AN;
        __syncthreads();
#pragma unroll
        for (int i = 0; i < 16; i++) {
            int e = tid + i * 256;
            int rr2 = e >> 7, d = e & 127;
            Ks[rr2 * QSTR + d] = Kg[(size_t)(k0 + rr2) * HDD + d];
            Vs[rr2 * HDD + d]  = Vg[(size_t)(k0 + rr2) * HDD + d];
        }
        __syncthreads();

        float s[4];
#pragma unroll
        for (int j = 0; j < 4; j++) {
            int c = g + 8 * j;
            const float4* qp = reinterpret_cast<const float4*>(Qs + r * QSTR);
            const float4* kp = reinterpret_cast<const float4*>(Ks + c * QSTR);
            float a = 0.f;
#pragma unroll
            for (int k4 = 0; k4 < 32; k4++) {
                float4 qa = qp[k4], ka = kp[k4];
                a += qa.x * ka.x + qa.y * ka.y + qa.z * ka.z + qa.w * ka.w;
            }
            if (k0 + c > q0 + r) a = -1e30f;
            s[j] = a;
        }
        float mx = fmaxf(fmaxf(s[0], s[1]), fmaxf(s[2], s[3]));
        mx = fmaxf(mx, __shfl_xor_sync(~0u, mx, 1));
        mx = fmaxf(mx, __shfl_xor_sync(~0u, mx, 2));
        mx = fmaxf(mx, __shfl_xor_sync(~0u, mx, 4));
        float m_new = fmaxf(m_r, mx);
        float p[4];
        float psum = 0.f;
#pragma unroll
        for (int j = 0; j < 4; j++) { p[j] = __expf(s[j] - m_new); psum += p[j]; }
        psum += __shfl_xor_sync(~0u, psum, 1);
        psum += __shfl_xor_sync(~0u, psum, 2);
        psum += __shfl_xor_sync(~0u, psum, 4);
        float alpha = __expf(m_r - m_new);
        m_r = m_new;
        l_r = l_r * alpha + psum;
#pragma unroll
        for (int t = 0; t < 16; t++) acc[t] *= alpha;

        const int lanebase = (r & 3) * 8;
#pragma unroll
        for (int c = 0; c < AN; c++) {
            float pv = __shfl_sync(~0u, p[c >> 3], lanebase + (c & 7), 32);
            const float4* vp = reinterpret_cast<const float4*>(Vs + c * HDD + d0);
#pragma unroll
            for (int t4 = 0; t4 < 4; t4++) {
                float4 va = vp[t4];
                acc[t4 * 4 + 0] = fmaf(pv, va.x, acc[t4 * 4 + 0]);
                acc[t4 * 4 + 1] = fmaf(pv, va.y, acc[t4 * 4 + 1]);
                acc[t4 * 4 + 2] = fmaf(pv, va.z, acc[t4 * 4 + 2]);
                acc[t4 * 4 + 3] = fmaf(pv, va.w, acc[t4 * 4 + 3]);
            }
        }
    }

    float inv_l = 1.f / l_r;
    float* Og = g_ao + ((size_t)(b * LL + q0 + r) * HH + h) * HDD + d0;
#pragma unroll
    for (int t4 = 0; t4 < 4; t4++) {
        float4 v;
        v.x = acc[t4 * 4 + 0] * inv_l; v.y = acc[t4 * 4 + 1] * inv_l;
        v.z = acc[t4 * 4 + 2] * inv_l; v.w = acc[t4 * 4 + 3] * inv_l;
        reinterpret_cast<float4*>(Og)[t4] = v;
    }
}

// ---------------- router ------------------------------------------------------
__global__ __launch_bounds__(128) void router_kernel(const float* __restrict__ rw)
{
    int n = blockIdx.x;
    const float* row = g_hm + (size_t)n * DMD;
    int w = threadIdx.x >> 5, lane = threadIdx.x & 31;
    __shared__ float logits[EE];
#pragma unroll
    for (int eb = 0; eb < 4; eb++) {
        int e = eb * 4 + w;
        const float* wr = rw + (size_t)e * DMD;
        float p = 0.f;
        for (int d = lane; d < DMD; d += 32) p += row[d] * wr[d];
#pragma unroll
        for (int o = 16; o > 0; o >>= 1) p += __shfl_xor_sync(~0u, p, o);
        if (lane == 0) logits[e] = p;
    }
    __syncthreads();
    if (threadIdx.x == 0) {
        float mx = -1e30f;
        for (int e = 0; e < EE; e++) mx = fmaxf(mx, logits[e]);
        float pr[EE];
        for (int e = 0; e < EE; e++) pr[e] = __expf(logits[e] - mx);
        bool used[EE];
        float wsel[EE];
        for (int e = 0; e < EE; e++) { used[e] = false; wsel[e] = 0.f; }
        float ssum = 0.f;
        for (int t = 0; t < TOPKK; t++) {
            float best = -1.f; int bi = 0;
            for (int e = 0; e < EE; e++)
                if (!used[e] && pr[e] > best) { best = pr[e]; bi = e; }
            used[bi] = true; wsel[bi] = best; ssum += best;
        }
        float inv = 1.f / ssum;
        for (int e = 0; e < EE; e++)
            g_wd[(size_t)n * EE + e] = used[e] ? wsel[e] * inv : 0.f;
    }
}

// -----------------------------------------------------------------------------
extern "C" void kernel_launch(void* const* d_in, const int* in_sizes, int n_in,
                              void* d_out, int out_size)
{
    const float* x    = (const float*)d_in[0];
    const float* cosb = (const float*)d_in[1];
    const float* sinb = (const float*)d_in[2];
    const float* naw  = (const float*)d_in[3];
    const float* q_w  = (const float*)d_in[4];
    const float* k_w  = (const float*)d_in[5];
    const float* v_w  = (const float*)d_in[6];
    const float* qn_w = (const float*)d_in[7];
    const float* kn_w = (const float*)d_in[8];
    const float* o_w  = (const float*)d_in[9];
    const float* nmw  = (const float*)d_in[10];
    const float* rw   = (const float*)d_in[11];
    const float* egw  = (const float*)d_in[12];
    const float* euw  = (const float*)d_in[13];
    const float* edw  = (const float*)d_in[14];
    float* out = (float*)d_out;

    static float *ph = nullptr, *pwqkv, *pqkv, *pao, *phm, *pgate, *pup, *pact;
    static bool init_done = false;
    if (!init_done) {
        cudaGetSymbolAddress((void**)&ph,    g_h);
        cudaGetSymbolAddress((void**)&pwqkv, g_wqkv);
        cudaGetSymbolAddress((void**)&pqkv,  g_qkv);
        cudaGetSymbolAddress((void**)&pao,   g_ao);
        cudaGetSymbolAddress((void**)&phm,   g_hm);
        cudaGetSymbolAddress((void**)&pgate, g_gate);
        cudaGetSymbolAddress((void**)&pup,   g_up);
        cudaGetSymbolAddress((void**)&pact,  g_act);
        cudaFuncSetAttribute(attn_kernel,
                             cudaFuncAttributeMaxDynamicSharedMemorySize, ATTN_SMEM);
        cudaFuncSetAttribute(gemm_ta<0>,
                             cudaFuncAttributeMaxDynamicSharedMemorySize, GEMM_SMEM);
        cudaFuncSetAttribute(gemm_ta<1>,
                             cudaFuncAttributeMaxDynamicSharedMemorySize, GEMM_SMEM);
        cudaFuncSetAttribute(gemm_ta<4>,
                             cudaFuncAttributeMaxDynamicSharedMemorySize, GEMM_SMEM);
        init_done = true;
    }

    // 0) concat qkv weights (D2D async copies; capture-legal)
    cudaMemcpyAsync(pwqkv, q_w, (size_t)HH * HDD * DMD * 4, cudaMemcpyDeviceToDevice);
    cudaMemcpyAsync(pwqkv + (size_t)HH * HDD * DMD, k_w,
                    (size_t)KVH * HDD * DMD * 4, cudaMemcpyDeviceToDevice);
    cudaMemcpyAsync(pwqkv + (size_t)(HH + KVH) * HDD * DMD, v_w,
                    (size_t)KVH * HDD * DMD * 4, cudaMemcpyDeviceToDevice);

    // 1) pre-attn norm
    rmsnorm_kernel<<<NTOK, 256>>>(x, naw, ph);

    // 2) fused QKV projection (N=5120)
    gemm_ta<0><<<dim3(NQKV / BN, NTOK / BM), 256, GEMM_SMEM>>>(ph, pwqkv, pqkv, nullptr, NQKV, DMD);

    // 3) per-head norm + RoPE + transpose
    qkv_post<<<dim3(HH + 2 * KVH, LL, BB), 128>>>(cosb, sinb, qn_w, kn_w);

    // 4) causal flash attention (fp32)
    attn_kernel<<<dim3(LL / AM, HH, BB), 256, ATTN_SMEM>>>();

    // 5) O projection + residual
    gemm_ta<1><<<dim3(DMD / BN, NTOK / BM), 256, GEMM_SMEM>>>(pao, o_w, out, x, DMD, HH * HDD);

    // 6) pre-MLP norm
    rmsnorm_kernel<<<NTOK, 256>>>(out, nmw, phm);

    // 7) router
    router_kernel<<<NTOK, 128>>>(rw);

    // 8) MoE gate and up as flat N=2048 GEMMs
    gemm_ta<0><<<dim3(EE * MII / BN, NTOK / BM), 256, GEMM_SMEM>>>(phm, egw, pgate, nullptr, EE * MII, DMD);
    gemm_ta<0><<<dim3(EE * MII / BN, NTOK / BM), 256, GEMM_SMEM>>>(phm, euw, pup,   nullptr, EE * MII, DMD);

    // 9) act = wd * silu(gate) * up
    moe_act_kernel<<<NTOK, 256>>>();

    // 10) MoE down proj: out += act @ dw^T (expert-blocked B, K=2048)
    gemm_ta<4><<<dim3(DMD / BN, NTOK / BM), 256, GEMM_SMEM>>>(pact, edw, out, nullptr, DMD, EE * MII);
}

// round 10
// speedup vs baseline: 4.0772x; 2.5725x over previous
#include <cuda_runtime.h>
#include <cstdint>

#define BB   4
#define LL   1024
#define DMD  2048
#define HH   32
#define KVH  4
#define HDD  128
#define GG   (HH / KVH)
#define EE   16
#define TOPKK 8
#define MII  128
#define NTOK (BB * LL)
#define EPSF 1e-6f
#define NQKV (HH * HDD + 2 * KVH * HDD)   // 5120

// GEMM tiling
#define BM 128
#define BN 128
#define BK 16
#define ASTR 20
#define NSTAGE 3
#define GEMM_SMEM (NSTAGE * (BM + BN) * ASTR * 4)   // 61440 bytes

// attention tiling
#define AQ 128
#define AK 64
#define QPAD 132
#define VPAD 68
#define PPAD 68
#define ATTN_SMEM ((AQ * QPAD + 2 * AK * QPAD + HDD * VPAD + 8 * 16 * PPAD) * 4) // 204800

// ---------------- scratch (device globals; no allocation allowed) ------------
__device__ float g_h   [NTOK * DMD];
__device__ float g_wqkv[NQKV * DMD];
__device__ float g_qkv [NTOK * NQKV];
__device__ float g_qt  [NTOK * HH  * HDD];  // (b,h,l,d)
__device__ float g_kt  [NTOK * KVH * HDD];  // (b,kv,l,d)
__device__ float g_vt  [NTOK * KVH * HDD];  // (b,kv,d,l)  TRANSPOSED
__device__ float g_ao  [NTOK * HH  * HDD];
__device__ float g_hm  [NTOK * DMD];
__device__ float g_wd  [NTOK * EE];
__device__ float g_gate[NTOK * EE * MII];
__device__ float g_up  [NTOK * EE * MII];
__device__ float g_act [NTOK * EE * MII];

// ---------------- helpers ----------------------------------------------------
__device__ __forceinline__ uint32_t s2u(const void* p) {
    return (uint32_t)__cvta_generic_to_shared(p);
}
__device__ __forceinline__ void cp16(uint32_t s, const void* g) {
    asm volatile("cp.async.cg.shared.global [%0], [%1], 16;\n" :: "r"(s), "l"(g));
}
__device__ __forceinline__ void cp_commit() {
    asm volatile("cp.async.commit_group;\n" ::: "memory");
}
__device__ __forceinline__ void cp_wait1() {
    asm volatile("cp.async.wait_group 1;\n" ::: "memory");
}
__device__ __forceinline__ void cp_wait2() {
    asm volatile("cp.async.wait_group 2;\n" ::: "memory");
}
__device__ __forceinline__ void mma8(float* c, const uint32_t* a, const uint32_t* b) {
    asm volatile(
        "mma.sync.aligned.m16n8k8.row.col.f32.tf32.tf32.f32 "
        "{%0,%1,%2,%3}, {%4,%5,%6,%7}, {%8,%9}, {%0,%1,%2,%3};\n"
        : "+f"(c[0]), "+f"(c[1]), "+f"(c[2]), "+f"(c[3])
        : "r"(a[0]), "r"(a[1]), "r"(a[2]), "r"(a[3]), "r"(b[0]), "r"(b[1]));
}

// ---------------- tf32 cp.async GEMM: C = A(MxK) @ B(NxK)^T ------------------
template<int MODE>
__global__ __launch_bounds__(256, 2) void gemm_ta(
    const float* __restrict__ A, const float* __restrict__ B,
    float* __restrict__ C, const float* __restrict__ aux, int N, int K)
{
    extern __shared__ float smem[];
    float* As = smem;
    float* Bs = smem + NSTAGE * BM * ASTR;
    const int tid  = threadIdx.x;
    const int row0 = blockIdx.y * BM;
    const int col0 = blockIdx.x * BN;
    const int warp = tid >> 5, lane = tid & 31;
    const int wr = (warp >> 2) * 64, wc = (warp & 3) * 32;
    const int lr = lane >> 2, lc = lane & 3;
    const int ldrow = tid >> 1, ldoff = (tid & 1) * 8;

    const float* Agp = A + (size_t)(row0 + ldrow) * K + ldoff;
    const float* Bgp = B + (size_t)(col0 + ldrow) * K + ldoff;

    float acc[4][4][4] = {};

#define ISSUE(cc) do {                                                         \
        int st_ = (cc) % NSTAGE; int k0_ = (cc) * BK;                          \
        uint32_t sa_ = s2u(&As[st_ * BM * ASTR + ldrow * ASTR + ldoff]);       \
        const float* ag_ = Agp + k0_;                                          \
        cp16(sa_, ag_); cp16(sa_ + 16, ag_ + 4);                               \
        const float* bg_ = (MODE == 4)                                         \
            ? B + (size_t)(k0_ >> 7) * ((size_t)DMD * MII)                     \
                + (size_t)(col0 + ldrow) * MII + (k0_ & 127) + ldoff           \
            : Bgp + k0_;                                                       \
        uint32_t sb_ = s2u(&Bs[st_ * BN * ASTR + ldrow * ASTR + ldoff]);       \
        cp16(sb_, bg_); cp16(sb_ + 16, bg_ + 4);                               \
    } while (0)

    ISSUE(0); cp_commit();
    ISSUE(1); cp_commit();

    const int nchunk = K / BK;
    for (int c = 0; c < nchunk; c++) {
        cp_wait1();
        __syncthreads();
        if (c + 2 < nchunk) ISSUE(c + 2);
        cp_commit();

        int st = c % NSTAGE;
        const uint32_t* sA = (const uint32_t*)(As + st * BM * ASTR);
        const uint32_t* sB = (const uint32_t*)(Bs + st * BN * ASTR);
#pragma unroll
        for (int ks = 0; ks < 2; ks++) {
            uint32_t af[4][4], bf[4][2];
#pragma unroll
            for (int mi = 0; mi < 4; mi++) {
                const uint32_t* p = sA + (wr + mi * 16 + lr) * ASTR + ks * 8 + lc;
                af[mi][0] = p[0];
                af[mi][1] = p[8 * ASTR];
                af[mi][2] = p[4];
                af[mi][3] = p[8 * ASTR + 4];
            }
#pragma unroll
            for (int ni = 0; ni < 4; ni++) {
                const uint32_t* p = sB + (wc + ni * 8 + lr) * ASTR + ks * 8 + lc;
                bf[ni][0] = p[0];
                bf[ni][1] = p[4];
            }
#pragma unroll
            for (int mi = 0; mi < 4; mi++)
#pragma unroll
                for (int ni = 0; ni < 4; ni++)
                    mma8(acc[mi][ni], af[mi], bf[ni]);
        }
    }
#undef ISSUE

#pragma unroll
    for (int mi = 0; mi < 4; mi++) {
        int r = row0 + wr + mi * 16 + lr;
#pragma unroll
        for (int ni = 0; ni < 4; ni++) {
            int cc = col0 + wc + ni * 8 + lc * 2;
            size_t i0 = (size_t)r * N + cc;
            size_t i1 = i0 + (size_t)8 * N;
            float2 v0 = make_float2(acc[mi][ni][0], acc[mi][ni][1]);
            float2 v1 = make_float2(acc[mi][ni][2], acc[mi][ni][3]);
            if (MODE == 1) {
                float2 a0 = *(const float2*)(aux + i0);
                float2 a1 = *(const float2*)(aux + i1);
                v0.x += a0.x; v0.y += a0.y; v1.x += a1.x; v1.y += a1.y;
            }
            if (MODE == 4) {
                float2 a0 = *(const float2*)(C + i0);
                float2 a1 = *(const float2*)(C + i1);
                v0.x += a0.x; v0.y += a0.y; v1.x += a1.x; v1.y += a1.y;
            }
            *(float2*)(C + i0) = v0;
            *(float2*)(C + i1) = v1;
        }
    }
}

// ---------------- MoE elementwise: act = wd * silu(gate) * up ----------------
__global__ __launch_bounds__(256) void moe_act_kernel()
{
    int n = blockIdx.x;
    const float4* gp = (const float4*)(g_gate + (size_t)n * EE * MII);
    const float4* up = (const float4*)(g_up   + (size_t)n * EE * MII);
    float4*       ap = (float4*)(g_act + (size_t)n * EE * MII);
    const float*  wdp = g_wd + (size_t)n * EE;
#pragma unroll
    for (int t = 0; t < 2; t++) {
        int i = threadIdx.x + t * 256;
        float w = wdp[(i * 4) >> 7];
        float4 g = gp[i], u = up[i], o;
        o.x = w * (g.x / (1.f + __expf(-g.x))) * u.x;
        o.y = w * (g.y / (1.f + __expf(-g.y))) * u.y;
        o.z = w * (g.z / (1.f + __expf(-g.z))) * u.z;
        o.w = w * (g.w / (1.f + __expf(-g.w))) * u.w;
        ap[i] = o;
    }
}

// ---------------- row RMSNorm over DM ----------------------------------------
__global__ __launch_bounds__(256) void rmsnorm_kernel(
    const float* __restrict__ x, const float* __restrict__ w, float* __restrict__ y)
{
    int row = blockIdx.x;
    const float* xr = x + (size_t)row * DMD;
    float ss = 0.f;
    for (int d = threadIdx.x; d < DMD; d += 256) { float v = xr[d]; ss += v * v; }
    __shared__ float red[8];
#pragma unroll
    for (int o = 16; o > 0; o >>= 1) ss += __shfl_xor_sync(~0u, ss, o);
    if ((threadIdx.x & 31) == 0) red[threadIdx.x >> 5] = ss;
    __syncthreads();
    if (threadIdx.x < 8) {
        float t = red[threadIdx.x];
#pragma unroll
        for (int o = 4; o > 0; o >>= 1) t += __shfl_xor_sync(0xffu, t, o);
        if (threadIdx.x == 0) red[0] = t;
    }
    __syncthreads();
    float scale = rsqrtf(red[0] / (float)DMD + EPSF);
    for (int d = threadIdx.x; d < DMD; d += 256)
        y[(size_t)row * DMD + d] = xr[d] * scale * w[d];
}

// -------- per-head RMSNorm + RoPE + transpose; V transposed to (d, l) --------
__global__ __launch_bounds__(128) void qkv_post(
    const float* __restrict__ cosb, const float* __restrict__ sinb,
    const float* __restrict__ qn_w, const float* __restrict__ kn_w)
{
    int b = blockIdx.z, l = blockIdx.y, rr = blockIdx.x;
    int d = threadIdx.x;
    int n = b * LL + l;
    __shared__ float buf[HDD];
    __shared__ float red[4];

    const float* src; float* dst; const float* nw;
    if (rr < HH) {
        src = g_qkv + (size_t)n * NQKV + rr * HDD;
        dst = g_qt + ((size_t)(b * HH + rr) * LL + l) * HDD;
        nw = qn_w;
    } else if (rr < HH + KVH) {
        int kv = rr - HH;
        src = g_qkv + (size_t)n * NQKV + HH * HDD + kv * HDD;
        dst = g_kt + ((size_t)(b * KVH + kv) * LL + l) * HDD;
        nw = kn_w;
    } else {
        int kv = rr - HH - KVH;
        // transposed store: g_vt[b][kv][d][l]
        g_vt[((size_t)(b * KVH + kv) * HDD + d) * LL + l] =
            g_qkv[(size_t)n * NQKV + (HH + KVH) * HDD + kv * HDD + d];
        return;
    }
    float v = src[d];
    float ss = v * v;
#pragma unroll
    for (int o = 16; o > 0; o >>= 1) ss += __shfl_xor_sync(~0u, ss, o);
    if ((d & 31) == 0) red[d >> 5] = ss;
    __syncthreads();
    float tot = red[0] + red[1] + red[2] + red[3];
    float nv = v * rsqrtf(tot / (float)HDD + EPSF) * nw[d];
    buf[d] = nv;
    __syncthreads();
    float other = (d < HDD / 2) ? -buf[d + HDD / 2] : buf[d - HDD / 2];
    float c = cosb[(size_t)n * HDD + d];
    float s = sinb[(size_t)n * HDD + d];
    dst[d] = c * nv + s * other;
}

// ---------------- tf32 tensor-core flash attention (causal, GQA) -------------
// BQ=128 rows/CTA, 8 warps of m16; k-tiles of 64. K double-buffered cp.async.
__global__ __launch_bounds__(256) void attn_kernel()
{
    extern __shared__ float sm[];
    float* Qs  = sm;                        // [128][132]
    float* Ksm = Qs + AQ * QPAD;            // [2][64][132]
    float* Vsm = Ksm + 2 * AK * QPAD;       // [128][68]  V^T tile: d rows, key cols
    float* Psm = Vsm + HDD * VPAD;          // [8 warps][16][68]

    const int tid = threadIdx.x;
    const int wid = tid >> 5, lane = tid & 31;
    const int lr = lane >> 2, lc = lane & 3;
    const int b = blockIdx.z, h = blockIdx.y;
    const int q0 = blockIdx.x * AQ;
    const int kv = h / GG;
    const int wq0 = wid * 16;
    const float SCALE = 0.08838834764831845f;   // 1/sqrt(128)

    const float* Qg = g_qt + ((size_t)(b * HH + h) * LL + q0) * HDD;
    const float* Kg = g_kt + ((size_t)(b * KVH + kv) * LL) * HDD;
    const float* Vg = g_vt + ((size_t)(b * KVH + kv) * HDD) * LL;  // [d][l]

    // prologue: Q tile + K tile 0
    {
        int r = tid >> 1, half = (tid & 1) * 64;
        const float* src = Qg + (size_t)r * HDD + half;
        uint32_t dst = s2u(Qs + r * QPAD + half);
#pragma unroll
        for (int j = 0; j < 16; j++) cp16(dst + j * 16, src + j * 4);
    }
    {
        int r = tid >> 2, q4 = (tid & 3) * 32;
        const float* src = Kg + (size_t)r * HDD + q4;
        uint32_t dst = s2u(Ksm + r * QPAD + q4);
#pragma unroll
        for (int j = 0; j < 8; j++) cp16(dst + j * 16, src + j * 4);
    }
    cp_commit();

    float oacc[16][4];
#pragma unroll
    for (int i = 0; i < 16; i++)
#pragma unroll
        for (int j = 0; j < 4; j++) oacc[i][j] = 0.f;
    float m0 = -1e30f, m1 = -1e30f, l0 = 0.f, l1 = 0.f;

    const int ntile = q0 / AK + 2;
    for (int kt = 0; kt < ntile; kt++) {
        int k0 = kt * AK;
        __syncthreads();   // prior readers of Vsm / K[(kt+1)&1] done
        // issue V[kt]  (V^T tile: 128 d-rows x 64 keys)
        {
            int r = tid >> 1, half = (tid & 1) * 32;
            const float* src = Vg + (size_t)r * LL + k0 + half;
            uint32_t dst = s2u(Vsm + r * VPAD + half);
#pragma unroll
            for (int j = 0; j < 8; j++) cp16(dst + j * 16, src + j * 4);
        }
        cp_commit();
        // issue K[kt+1]
        if (kt + 1 < ntile) {
            int r = tid >> 2, q4 = (tid & 3) * 32;
            const float* src = Kg + (size_t)(k0 + AK + r) * HDD + q4;
            uint32_t dst = s2u(Ksm + ((kt + 1) & 1) * AK * QPAD + r * QPAD + q4);
#pragma unroll
            for (int j = 0; j < 8; j++) cp16(dst + j * 16, src + j * 4);
        }
        cp_commit();
        cp_wait2();        // K[kt] (and Q) complete
        __syncthreads();

        // ---- S = Q @ K^T  (per warp: m16 x n64) ----
        const uint32_t* sQ = (const uint32_t*)Qs;
        const uint32_t* sK = (const uint32_t*)(Ksm + (kt & 1) * AK * QPAD);
        float sacc[8][4] = {};
#pragma unroll
        for (int ks = 0; ks < 16; ks++) {
            uint32_t a[4];
            const uint32_t* qp = sQ + (wq0 + lr) * QPAD + ks * 8 + lc;
            a[0] = qp[0]; a[1] = qp[8 * QPAD]; a[2] = qp[4]; a[3] = qp[8 * QPAD + 4];
#pragma unroll
            for (int ni = 0; ni < 8; ni++) {
                uint32_t bb[2];
                const uint32_t* kp = sK + (ni * 8 + lr) * QPAD + ks * 8 + lc;
                bb[0] = kp[0]; bb[1] = kp[4];
                mma8(sacc[ni], a, bb);
            }
        }

        // ---- mask + scale + online softmax ----
        const int grow0 = q0 + wq0 + lr;
        const int grow1 = grow0 + 8;
        const bool maskt = (k0 + AK > q0);
        float mx0 = -1e30f, mx1 = -1e30f;
#pragma unroll
        for (int ni = 0; ni < 8; ni++) {
            int gc = k0 + ni * 8 + 2 * lc;
            float s0 = sacc[ni][0] * SCALE, s1 = sacc[ni][1] * SCALE;
            float s2 = sacc[ni][2] * SCALE, s3 = sacc[ni][3] * SCALE;
            if (maskt) {
                if (gc     > grow0) s0 = -1e30f;
                if (gc + 1 > grow0) s1 = -1e30f;
                if (gc     > grow1) s2 = -1e30f;
                if (gc + 1 > grow1) s3 = -1e30f;
            }
            sacc[ni][0] = s0; sacc[ni][1] = s1; sacc[ni][2] = s2; sacc[ni][3] = s3;
            mx0 = fmaxf(mx0, fmaxf(s0, s1));
            mx1 = fmaxf(mx1, fmaxf(s2, s3));
        }
        mx0 = fmaxf(mx0, __shfl_xor_sync(~0u, mx0, 1));
        mx0 = fmaxf(mx0, __shfl_xor_sync(~0u, mx0, 2));
        mx1 = fmaxf(mx1, __shfl_xor_sync(~0u, mx1, 1));
        mx1 = fmaxf(mx1, __shfl_xor_sync(~0u, mx1, 2));
        float mn0 = fmaxf(m0, mx0), mn1 = fmaxf(m1, mx1);
        float al0 = __expf(m0 - mn0), al1 = __expf(m1 - mn1);
        m0 = mn0; m1 = mn1;

        float* Pw = Psm + wid * 16 * PPAD;
        float sum0 = 0.f, sum1 = 0.f;
#pragma unroll
        for (int ni = 0; ni < 8; ni++) {
            float p0 = __expf(sacc[ni][0] - mn0);
            float p1 = __expf(sacc[ni][1] - mn0);
            float p2 = __expf(sacc[ni][2] - mn1);
            float p3 = __expf(sacc[ni][3] - mn1);
            sum0 += p0 + p1; sum1 += p2 + p3;
            *(float2*)(Pw + lr * PPAD + ni * 8 + 2 * lc)       = make_float2(p0, p1);
            *(float2*)(Pw + (lr + 8) * PPAD + ni * 8 + 2 * lc) = make_float2(p2, p3);
        }
        sum0 += __shfl_xor_sync(~0u, sum0, 1);
        sum0 += __shfl_xor_sync(~0u, sum0, 2);
        sum1 += __shfl_xor_sync(~0u, sum1, 1);
        sum1 += __shfl_xor_sync(~0u, sum1, 2);
        l0 = l0 * al0 + sum0;
        l1 = l1 * al1 + sum1;
#pragma unroll
        for (int ni = 0; ni < 16; ni++) {
            oacc[ni][0] *= al0; oacc[ni][1] *= al0;
            oacc[ni][2] *= al1; oacc[ni][3] *= al1;
        }

        cp_wait1();        // V[kt] complete
        __syncthreads();   // also makes Pw stores visible

        // ---- O += P @ V  (per warp: m16 x n128, k=64) ----
        const uint32_t* sP = (const uint32_t*)Pw;
        const uint32_t* sV = (const uint32_t*)Vsm;
#pragma unroll
        for (int ks = 0; ks < 8; ks++) {
            uint32_t a[4];
            const uint32_t* pp = sP + lr * PPAD + ks * 8 + lc;
            a[0] = pp[0]; a[1] = pp[8 * PPAD]; a[2] = pp[4]; a[3] = pp[8 * PPAD + 4];
#pragma unroll
            for (int ni = 0; ni < 16; ni++) {
                uint32_t bb[2];
                const uint32_t* vp = sV + (ni * 8 + lr) * VPAD + ks * 8 + lc;
                bb[0] = vp[0]; bb[1] = vp[4];
                mma8(oacc[ni], a, bb);
            }
        }
    }

    // epilogue: normalize and store to (token, h, d)
    float inv0 = 1.f / l0, inv1 = 1.f / l1;
    int row0g = q0 + wq0 + lr;
    float* O0 = g_ao + ((size_t)(b * LL + row0g) * HH + h) * HDD;
    float* O1 = g_ao + ((size_t)(b * LL + row0g + 8) * HH + h) * HDD;
#pragma unroll
    for (int ni = 0; ni < 16; ni++) {
        int d = ni * 8 + 2 * lc;
        *(float2*)(O0 + d) = make_float2(oacc[ni][0] * inv0, oacc[ni][1] * inv0);
        *(float2*)(O1 + d) = make_float2(oacc[ni][2] * inv1, oacc[ni][3] * inv1);
    }
}

// ---------------- router ------------------------------------------------------
__global__ __launch_bounds__(128) void router_kernel(const float* __restrict__ rw)
{
    int n = blockIdx.x;
    const float* row = g_hm + (size_t)n * DMD;
    int w = threadIdx.x >> 5, lane = threadIdx.x & 31;
    __shared__ float logits[EE];
#pragma unroll
    for (int eb = 0; eb < 4; eb++) {
        int e = eb * 4 + w;
        const float* wr = rw + (size_t)e * DMD;
        float p = 0.f;
        for (int d = lane; d < DMD; d += 32) p += row[d] * wr[d];
#pragma unroll
        for (int o = 16; o > 0; o >>= 1) p += __shfl_xor_sync(~0u, p, o);
        if (lane == 0) logits[e] = p;
    }
    __syncthreads();
    if (threadIdx.x == 0) {
        float mx = -1e30f;
        for (int e = 0; e < EE; e++) mx = fmaxf(mx, logits[e]);
        float pr[EE];
        for (int e = 0; e < EE; e++) pr[e] = __expf(logits[e] - mx);
        bool used[EE];
        float wsel[EE];
        for (int e = 0; e < EE; e++) { used[e] = false; wsel[e] = 0.f; }
        float ssum = 0.f;
        for (int t = 0; t < TOPKK; t++) {
            float best = -1.f; int bi = 0;
            for (int e = 0; e < EE; e++)
                if (!used[e] && pr[e] > best) { best = pr[e]; bi = e; }
            used[bi] = true; wsel[bi] = best; ssum += best;
        }
        float inv = 1.f / ssum;
        for (int e = 0; e < EE; e++)
            g_wd[(size_t)n * EE + e] = used[e] ? wsel[e] * inv : 0.f;
    }
}

// -----------------------------------------------------------------------------
extern "C" void kernel_launch(void* const* d_in, const int* in_sizes, int n_in,
                              void* d_out, int out_size)
{
    const float* x    = (const float*)d_in[0];
    const float* cosb = (const float*)d_in[1];
    const float* sinb = (const float*)d_in[2];
    const float* naw  = (const float*)d_in[3];
    const float* q_w  = (const float*)d_in[4];
    const float* k_w  = (const float*)d_in[5];
    const float* v_w  = (const float*)d_in[6];
    const float* qn_w = (const float*)d_in[7];
    const float* kn_w = (const float*)d_in[8];
    const float* o_w  = (const float*)d_in[9];
    const float* nmw  = (const float*)d_in[10];
    const float* rw   = (const float*)d_in[11];
    const float* egw  = (const float*)d_in[12];
    const float* euw  = (const float*)d_in[13];
    const float* edw  = (const float*)d_in[14];
    float* out = (float*)d_out;

    static float *ph = nullptr, *pwqkv, *pqkv, *pao, *phm, *pgate, *pup, *pact;
    static bool init_done = false;
    if (!init_done) {
        cudaGetSymbolAddress((void**)&ph,    g_h);
        cudaGetSymbolAddress((void**)&pwqkv, g_wqkv);
        cudaGetSymbolAddress((void**)&pqkv,  g_qkv);
        cudaGetSymbolAddress((void**)&pao,   g_ao);
        cudaGetSymbolAddress((void**)&phm,   g_hm);
        cudaGetSymbolAddress((void**)&pgate, g_gate);
        cudaGetSymbolAddress((void**)&pup,   g_up);
        cudaGetSymbolAddress((void**)&pact,  g_act);
        cudaFuncSetAttribute(attn_kernel,
                             cudaFuncAttributeMaxDynamicSharedMemorySize, ATTN_SMEM);
        cudaFuncSetAttribute(gemm_ta<0>,
                             cudaFuncAttributeMaxDynamicSharedMemorySize, GEMM_SMEM);
        cudaFuncSetAttribute(gemm_ta<1>,
                             cudaFuncAttributeMaxDynamicSharedMemorySize, GEMM_SMEM);
        cudaFuncSetAttribute(gemm_ta<4>,
                             cudaFuncAttributeMaxDynamicSharedMemorySize, GEMM_SMEM);
        init_done = true;
    }

    // 0) concat qkv weights
    cudaMemcpyAsync(pwqkv, q_w, (size_t)HH * HDD * DMD * 4, cudaMemcpyDeviceToDevice);
    cudaMemcpyAsync(pwqkv + (size_t)HH * HDD * DMD, k_w,
                    (size_t)KVH * HDD * DMD * 4, cudaMemcpyDeviceToDevice);
    cudaMemcpyAsync(pwqkv + (size_t)(HH + KVH) * HDD * DMD, v_w,
                    (size_t)KVH * HDD * DMD * 4, cudaMemcpyDeviceToDevice);

    // 1) pre-attn norm
    rmsnorm_kernel<<<NTOK, 256>>>(x, naw, ph);

    // 2) fused QKV projection (N=5120)
    gemm_ta<0><<<dim3(NQKV / BN, NTOK / BM), 256, GEMM_SMEM>>>(ph, pwqkv, pqkv, nullptr, NQKV, DMD);

    // 3) per-head norm + RoPE + transpose (V transposed to (d,l))
    qkv_post<<<dim3(HH + 2 * KVH, LL, BB), 128>>>(cosb, sinb, qn_w, kn_w);

    // 4) tf32 tensor-core flash attention
    attn_kernel<<<dim3(LL / AQ, HH, BB), 256, ATTN_SMEM>>>();

    // 5) O projection + residual
    gemm_ta<1><<<dim3(DMD / BN, NTOK / BM), 256, GEMM_SMEM>>>(pao, o_w, out, x, DMD, HH * HDD);

    // 6) pre-MLP norm
    rmsnorm_kernel<<<NTOK, 256>>>(out, nmw, phm);

    // 7) router
    router_kernel<<<NTOK, 128>>>(rw);

    // 8) MoE gate and up as flat N=2048 GEMMs
    gemm_ta<0><<<dim3(EE * MII / BN, NTOK / BM), 256, GEMM_SMEM>>>(phm, egw, pgate, nullptr, EE * MII, DMD);
    gemm_ta<0><<<dim3(EE * MII / BN, NTOK / BM), 256, GEMM_SMEM>>>(phm, euw, pup,   nullptr, EE * MII, DMD);

    // 9) act = wd * silu(gate) * up
    moe_act_kernel<<<NTOK, 256>>>();

    // 10) MoE down proj: out += act @ dw^T (expert-blocked B, K=2048)
    gemm_ta<4><<<dim3(DMD / BN, NTOK / BM), 256, GEMM_SMEM>>>(pact, edw, out, nullptr, DMD, EE * MII);
}

// round 16
// speedup vs baseline: 4.0932x; 1.0039x over previous
#include <cuda_runtime.h>
#include <cstdint>

#define BB   4
#define LL   1024
#define DMD  2048
#define HH   32
#define KVH  4
#define HDD  128
#define GG   (HH / KVH)
#define EE   16
#define TOPKK 8
#define MII  128
#define NTOK (BB * LL)
#define EPSF 1e-6f
#define NQKV (HH * HDD + 2 * KVH * HDD)   // 5120

// GEMM tiling
#define BM 128
#define BN 128
#define BK 16
#define ASTR 20
#define NSTAGE 4
#define GEMM_SMEM (NSTAGE * (BM + BN) * ASTR * 4)   // 81920 bytes

// attention tiling
#define AQ 128
#define AK 64
#define QPAD 132
#define VPAD 68
#define PPAD 68
#define ATTN_SMEM ((AQ * QPAD + 2 * AK * QPAD + HDD * VPAD + 8 * 16 * PPAD) * 4) // 204800

// ---------------- scratch (device globals; no allocation allowed) ------------
__device__ float g_h   [NTOK * DMD];
__device__ float g_wqkv[NQKV * DMD];
__device__ float g_qkv [NTOK * NQKV];
__device__ float g_qt  [NTOK * HH  * HDD];
__device__ float g_kt  [NTOK * KVH * HDD];
__device__ float g_vt  [NTOK * KVH * HDD];  // (b,kv,d,l) transposed
__device__ float g_ao  [NTOK * HH  * HDD];
__device__ float g_hm  [NTOK * DMD];
__device__ float g_wd  [NTOK * EE];
__device__ float g_gate[NTOK * EE * MII];
__device__ float g_up  [NTOK * EE * MII];
__device__ float g_act [NTOK * EE * MII];

// ---------------- helpers ----------------------------------------------------
__device__ __forceinline__ uint32_t s2u(const void* p) {
    return (uint32_t)__cvta_generic_to_shared(p);
}
__device__ __forceinline__ void cp16(uint32_t s, const void* g) {
    asm volatile("cp.async.cg.shared.global [%0], [%1], 16;\n" :: "r"(s), "l"(g));
}
__device__ __forceinline__ void cp_commit() {
    asm volatile("cp.async.commit_group;\n" ::: "memory");
}
__device__ __forceinline__ void cp_wait1() {
    asm volatile("cp.async.wait_group 1;\n" ::: "memory");
}
__device__ __forceinline__ void cp_wait2() {
    asm volatile("cp.async.wait_group 2;\n" ::: "memory");
}
__device__ __forceinline__ void mma8(float* c, const uint32_t* a, const uint32_t* b) {
    asm volatile(
        "mma.sync.aligned.m16n8k8.row.col.f32.tf32.tf32.f32 "
        "{%0,%1,%2,%3}, {%4,%5,%6,%7}, {%8,%9}, {%0,%1,%2,%3};\n"
        : "+f"(c[0]), "+f"(c[1]), "+f"(c[2]), "+f"(c[3])
        : "r"(a[0]), "r"(a[1]), "r"(a[2]), "r"(a[3]), "r"(b[0]), "r"(b[1]));
}

// ---------------- tf32 cp.async GEMM: C = A(MxK) @ B(NxK)^T ------------------
// MODE 0: C = acc   MODE 1: C = aux + acc   MODE 4: C += acc, B expert-blocked
// MODE 4 B layout: B(n,k) = Dw[k>>7][n][k&127]
// 4-stage pipeline: 2 chunk-loads kept in flight.
template<int MODE>
__global__ __launch_bounds__(256, 2) void gemm_ta(
    const float* __restrict__ A, const float* __restrict__ B,
    float* __restrict__ C, const float* __restrict__ aux, int N, int K)
{
    extern __shared__ float smem[];
    float* As = smem;
    float* Bs = smem + NSTAGE * BM * ASTR;
    const int tid  = threadIdx.x;
    const int row0 = blockIdx.y * BM;
    const int col0 = blockIdx.x * BN;
    const int warp = tid >> 5, lane = tid & 31;
    const int wr = (warp >> 2) * 64, wc = (warp & 3) * 32;
    const int lr = lane >> 2, lc = lane & 3;
    const int ldrow = tid >> 1, ldoff = (tid & 1) * 8;

    const float* Agp = A + (size_t)(row0 + ldrow) * K + ldoff;
    const float* Bgp = B + (size_t)(col0 + ldrow) * K + ldoff;

    float acc[4][4][4] = {};

#define ISSUE(cc) do {                                                         \
        int st_ = (cc) % NSTAGE; int k0_ = (cc) * BK;                          \
        uint32_t sa_ = s2u(&As[st_ * BM * ASTR + ldrow * ASTR + ldoff]);       \
        const float* ag_ = Agp + k0_;                                          \
        cp16(sa_, ag_); cp16(sa_ + 16, ag_ + 4);                               \
        const float* bg_ = (MODE == 4)                                         \
            ? B + (size_t)(k0_ >> 7) * ((size_t)DMD * MII)                     \
                + (size_t)(col0 + ldrow) * MII + (k0_ & 127) + ldoff           \
            : Bgp + k0_;                                                       \
        uint32_t sb_ = s2u(&Bs[st_ * BN * ASTR + ldrow * ASTR + ldoff]);       \
        cp16(sb_, bg_); cp16(sb_ + 16, bg_ + 4);                               \
    } while (0)

    ISSUE(0); cp_commit();
    ISSUE(1); cp_commit();
    ISSUE(2); cp_commit();

    const int nchunk = K / BK;
    for (int c = 0; c < nchunk; c++) {
        cp_wait2();          // chunk c resolved; c+1, c+2 may remain in flight
        __syncthreads();
        if (c + 3 < nchunk) ISSUE(c + 3);
        cp_commit();

        int st = c % NSTAGE;
        const uint32_t* sA = (const uint32_t*)(As + st * BM * ASTR);
        const uint32_t* sB = (const uint32_t*)(Bs + st * BN * ASTR);
#pragma unroll
        for (int ks = 0; ks < 2; ks++) {
            uint32_t af[4][4], bf[4][2];
#pragma unroll
            for (int mi = 0; mi < 4; mi++) {
                const uint32_t* p = sA + (wr + mi * 16 + lr) * ASTR + ks * 8 + lc;
                af[mi][0] = p[0];
                af[mi][1] = p[8 * ASTR];
                af[mi][2] = p[4];
                af[mi][3] = p[8 * ASTR + 4];
            }
#pragma unroll
            for (int ni = 0; ni < 4; ni++) {
                const uint32_t* p = sB + (wc + ni * 8 + lr) * ASTR + ks * 8 + lc;
                bf[ni][0] = p[0];
                bf[ni][1] = p[4];
            }
#pragma unroll
            for (int mi = 0; mi < 4; mi++)
#pragma unroll
                for (int ni = 0; ni < 4; ni++)
                    mma8(acc[mi][ni], af[mi], bf[ni]);
        }
    }
#undef ISSUE

#pragma unroll
    for (int mi = 0; mi < 4; mi++) {
        int r = row0 + wr + mi * 16 + lr;
#pragma unroll
        for (int ni = 0; ni < 4; ni++) {
            int cc = col0 + wc + ni * 8 + lc * 2;
            size_t i0 = (size_t)r * N + cc;
            size_t i1 = i0 + (size_t)8 * N;
            float2 v0 = make_float2(acc[mi][ni][0], acc[mi][ni][1]);
            float2 v1 = make_float2(acc[mi][ni][2], acc[mi][ni][3]);
            if (MODE == 1) {
                float2 a0 = *(const float2*)(aux + i0);
                float2 a1 = *(const float2*)(aux + i1);
                v0.x += a0.x; v0.y += a0.y; v1.x += a1.x; v1.y += a1.y;
            }
            if (MODE == 4) {
                float2 a0 = *(const float2*)(C + i0);
                float2 a1 = *(const float2*)(C + i1);
                v0.x += a0.x; v0.y += a0.y; v1.x += a1.x; v1.y += a1.y;
            }
            *(float2*)(C + i0) = v0;
            *(float2*)(C + i1) = v1;
        }
    }
}

// ---------------- MoE elementwise: act = wd * silu(gate) * up ----------------
__global__ __launch_bounds__(256) void moe_act_kernel()
{
    int n = blockIdx.x;
    const float4* gp = (const float4*)(g_gate + (size_t)n * EE * MII);
    const float4* up = (const float4*)(g_up   + (size_t)n * EE * MII);
    float4*       ap = (float4*)(g_act + (size_t)n * EE * MII);
    const float*  wdp = g_wd + (size_t)n * EE;
#pragma unroll
    for (int t = 0; t < 2; t++) {
        int i = threadIdx.x + t * 256;
        float w = wdp[(i * 4) >> 7];
        float4 g = gp[i], u = up[i], o;
        o.x = w * (g.x / (1.f + __expf(-g.x))) * u.x;
        o.y = w * (g.y / (1.f + __expf(-g.y))) * u.y;
        o.z = w * (g.z / (1.f + __expf(-g.z))) * u.z;
        o.w = w * (g.w / (1.f + __expf(-g.w))) * u.w;
        ap[i] = o;
    }
}

// ---------------- row RMSNorm over DM ----------------------------------------
__global__ __launch_bounds__(256) void rmsnorm_kernel(
    const float* __restrict__ x, const float* __restrict__ w, float* __restrict__ y)
{
    int row = blockIdx.x;
    const float* xr = x + (size_t)row * DMD;
    float ss = 0.f;
    for (int d = threadIdx.x; d < DMD; d += 256) { float v = xr[d]; ss += v * v; }
    __shared__ float red[8];
#pragma unroll
    for (int o = 16; o > 0; o >>= 1) ss += __shfl_xor_sync(~0u, ss, o);
    if ((threadIdx.x & 31) == 0) red[threadIdx.x >> 5] = ss;
    __syncthreads();
    if (threadIdx.x < 8) {
        float t = red[threadIdx.x];
#pragma unroll
        for (int o = 4; o > 0; o >>= 1) t += __shfl_xor_sync(0xffu, t, o);
        if (threadIdx.x == 0) red[0] = t;
    }
    __syncthreads();
    float scale = rsqrtf(red[0] / (float)DMD + EPSF);
    for (int d = threadIdx.x; d < DMD; d += 256)
        y[(size_t)row * DMD + d] = xr[d] * scale * w[d];
}

// -------- per-head RMSNorm + RoPE + transpose; V transposed to (d, l) --------
__global__ __launch_bounds__(128) void qkv_post(
    const float* __restrict__ cosb, const float* __restrict__ sinb,
    const float* __restrict__ qn_w, const float* __restrict__ kn_w)
{
    int b = blockIdx.z, l = blockIdx.y, rr = blockIdx.x;
    int d = threadIdx.x;
    int n = b * LL + l;
    __shared__ float buf[HDD];
    __shared__ float red[4];

    const float* src; float* dst; const float* nw;
    if (rr < HH) {
        src = g_qkv + (size_t)n * NQKV + rr * HDD;
        dst = g_qt + ((size_t)(b * HH + rr) * LL + l) * HDD;
        nw = qn_w;
    } else if (rr < HH + KVH) {
        int kv = rr - HH;
        src = g_qkv + (size_t)n * NQKV + HH * HDD + kv * HDD;
        dst = g_kt + ((size_t)(b * KVH + kv) * LL + l) * HDD;
        nw = kn_w;
    } else {
        int kv = rr - HH - KVH;
        g_vt[((size_t)(b * KVH + kv) * HDD + d) * LL + l] =
            g_qkv[(size_t)n * NQKV + (HH + KVH) * HDD + kv * HDD + d];
        return;
    }
    float v = src[d];
    float ss = v * v;
#pragma unroll
    for (int o = 16; o > 0; o >>= 1) ss += __shfl_xor_sync(~0u, ss, o);
    if ((d & 31) == 0) red[d >> 5] = ss;
    __syncthreads();
    float tot = red[0] + red[1] + red[2] + red[3];
    float nv = v * rsqrtf(tot / (float)HDD + EPSF) * nw[d];
    buf[d] = nv;
    __syncthreads();
    float other = (d < HDD / 2) ? -buf[d + HDD / 2] : buf[d - HDD / 2];
    float c = cosb[(size_t)n * HDD + d];
    float s = sinb[(size_t)n * HDD + d];
    dst[d] = c * nv + s * other;
}

// ---------------- tf32 tensor-core flash attention (causal, GQA) -------------
__global__ __launch_bounds__(256) void attn_kernel()
{
    extern __shared__ float sm[];
    float* Qs  = sm;                        // [128][132]
    float* Ksm = Qs + AQ * QPAD;            // [2][64][132]
    float* Vsm = Ksm + 2 * AK * QPAD;       // [128][68]
    float* Psm = Vsm + HDD * VPAD;          // [8][16][68]

    const int tid = threadIdx.x;
    const int wid = tid >> 5, lane = tid & 31;
    const int lr = lane >> 2, lc = lane & 3;
    const int b = blockIdx.z, h = blockIdx.y;
    const int q0 = blockIdx.x * AQ;
    const int kv = h / GG;
    const int wq0 = wid * 16;
    const float SCALE = 0.08838834764831845f;

    const float* Qg = g_qt + ((size_t)(b * HH + h) * LL + q0) * HDD;
    const float* Kg = g_kt + ((size_t)(b * KVH + kv) * LL) * HDD;
    const float* Vg = g_vt + ((size_t)(b * KVH + kv) * HDD) * LL;

    {
        int r = tid >> 1, half = (tid & 1) * 64;
        const float* src = Qg + (size_t)r * HDD + half;
        uint32_t dst = s2u(Qs + r * QPAD + half);
#pragma unroll
        for (int j = 0; j < 16; j++) cp16(dst + j * 16, src + j * 4);
    }
    {
        int r = tid >> 2, q4 = (tid & 3) * 32;
        const float* src = Kg + (size_t)r * HDD + q4;
        uint32_t dst = s2u(Ksm + r * QPAD + q4);
#pragma unroll
        for (int j = 0; j < 8; j++) cp16(dst + j * 16, src + j * 4);
    }
    cp_commit();

    float oacc[16][4];
#pragma unroll
    for (int i = 0; i < 16; i++)
#pragma unroll
        for (int j = 0; j < 4; j++) oacc[i][j] = 0.f;
    float m0 = -1e30f, m1 = -1e30f, l0 = 0.f, l1 = 0.f;

    const int ntile = q0 / AK + 2;
    for (int kt = 0; kt < ntile; kt++) {
        int k0 = kt * AK;
        __syncthreads();
        {
            int r = tid >> 1, half = (tid & 1) * 32;
            const float* src = Vg + (size_t)r * LL + k0 + half;
            uint32_t dst = s2u(Vsm + r * VPAD + half);
#pragma unroll
            for (int j = 0; j < 8; j++) cp16(dst + j * 16, src + j * 4);
        }
        cp_commit();
        if (kt + 1 < ntile) {
            int r = tid >> 2, q4 = (tid & 3) * 32;
            const float* src = Kg + (size_t)(k0 + AK + r) * HDD + q4;
            uint32_t dst = s2u(Ksm + ((kt + 1) & 1) * AK * QPAD + r * QPAD + q4);
#pragma unroll
            for (int j = 0; j < 8; j++) cp16(dst + j * 16, src + j * 4);
        }
        cp_commit();
        cp_wait2();
        __syncthreads();

        const uint32_t* sQ = (const uint32_t*)Qs;
        const uint32_t* sK = (const uint32_t*)(Ksm + (kt & 1) * AK * QPAD);
        float sacc[8][4] = {};
#pragma unroll
        for (int ks = 0; ks < 16; ks++) {
            uint32_t a[4];
            const uint32_t* qp = sQ + (wq0 + lr) * QPAD + ks * 8 + lc;
            a[0] = qp[0]; a[1] = qp[8 * QPAD]; a[2] = qp[4]; a[3] = qp[8 * QPAD + 4];
#pragma unroll
            for (int ni = 0; ni < 8; ni++) {
                uint32_t bb[2];
                const uint32_t* kp = sK + (ni * 8 + lr) * QPAD + ks * 8 + lc;
                bb[0] = kp[0]; bb[1] = kp[4];
                mma8(sacc[ni], a, bb);
            }
        }

        const int grow0 = q0 + wq0 + lr;
        const int grow1 = grow0 + 8;
        const bool maskt = (k0 + AK > q0);
        float mx0 = -1e30f, mx1 = -1e30f;
#pragma unroll
        for (int ni = 0; ni < 8; ni++) {
            int gc = k0 + ni * 8 + 2 * lc;
            float s0 = sacc[ni][0] * SCALE, s1 = sacc[ni][1] * SCALE;
            float s2 = sacc[ni][2] * SCALE, s3 = sacc[ni][3] * SCALE;
            if (maskt) {
                if (gc     > grow0) s0 = -1e30f;
                if (gc + 1 > grow0) s1 = -1e30f;
                if (gc     > grow1) s2 = -1e30f;
                if (gc + 1 > grow1) s3 = -1e30f;
            }
            sacc[ni][0] = s0; sacc[ni][1] = s1; sacc[ni][2] = s2; sacc[ni][3] = s3;
            mx0 = fmaxf(mx0, fmaxf(s0, s1));
            mx1 = fmaxf(mx1, fmaxf(s2, s3));
        }
        mx0 = fmaxf(mx0, __shfl_xor_sync(~0u, mx0, 1));
        mx0 = fmaxf(mx0, __shfl_xor_sync(~0u, mx0, 2));
        mx1 = fmaxf(mx1, __shfl_xor_sync(~0u, mx1, 1));
        mx1 = fmaxf(mx1, __shfl_xor_sync(~0u, mx1, 2));
        float mn0 = fmaxf(m0, mx0), mn1 = fmaxf(m1, mx1);
        float al0 = __expf(m0 - mn0), al1 = __expf(m1 - mn1);
        m0 = mn0; m1 = mn1;

        float* Pw = Psm + wid * 16 * PPAD;
        float sum0 = 0.f, sum1 = 0.f;
#pragma unroll
        for (int ni = 0; ni < 8; ni++) {
            float p0 = __expf(sacc[ni][0] - mn0);
            float p1 = __expf(sacc[ni][1] - mn0);
            float p2 = __expf(sacc[ni][2] - mn1);
            float p3 = __expf(sacc[ni][3] - mn1);
            sum0 += p0 + p1; sum1 += p2 + p3;
            *(float2*)(Pw + lr * PPAD + ni * 8 + 2 * lc)       = make_float2(p0, p1);
            *(float2*)(Pw + (lr + 8) * PPAD + ni * 8 + 2 * lc) = make_float2(p2, p3);
        }
        sum0 += __shfl_xor_sync(~0u, sum0, 1);
        sum0 += __shfl_xor_sync(~0u, sum0, 2);
        sum1 += __shfl_xor_sync(~0u, sum1, 1);
        sum1 += __shfl_xor_sync(~0u, sum1, 2);
        l0 = l0 * al0 + sum0;
        l1 = l1 * al1 + sum1;
#pragma unroll
        for (int ni = 0; ni < 16; ni++) {
            oacc[ni][0] *= al0; oacc[ni][1] *= al0;
            oacc[ni][2] *= al1; oacc[ni][3] *= al1;
        }

        cp_wait1();
        __syncthreads();

        const uint32_t* sP = (const uint32_t*)Pw;
        const uint32_t* sV = (const uint32_t*)Vsm;
#pragma unroll
        for (int ks = 0; ks < 8; ks++) {
            uint32_t a[4];
            const uint32_t* pp = sP + lr * PPAD + ks * 8 + lc;
            a[0] = pp[0]; a[1] = pp[8 * PPAD]; a[2] = pp[4]; a[3] = pp[8 * PPAD + 4];
#pragma unroll
            for (int ni = 0; ni < 16; ni++) {
                uint32_t bb[2];
                const uint32_t* vp = sV + (ni * 8 + lr) * VPAD + ks * 8 + lc;
                bb[0] = vp[0]; bb[1] = vp[4];
                mma8(oacc[ni], a, bb);
            }
        }
    }

    float inv0 = 1.f / l0, inv1 = 1.f / l1;
    int row0g = q0 + wq0 + lr;
    float* O0 = g_ao + ((size_t)(b * LL + row0g) * HH + h) * HDD;
    float* O1 = g_ao + ((size_t)(b * LL + row0g + 8) * HH + h) * HDD;
#pragma unroll
    for (int ni = 0; ni < 16; ni++) {
        int d = ni * 8 + 2 * lc;
        *(float2*)(O0 + d) = make_float2(oacc[ni][0] * inv0, oacc[ni][1] * inv0);
        *(float2*)(O1 + d) = make_float2(oacc[ni][2] * inv1, oacc[ni][3] * inv1);
    }
}

// ---------------- router ------------------------------------------------------
__global__ __launch_bounds__(128) void router_kernel(const float* __restrict__ rw)
{
    int n = blockIdx.x;
    const float* row = g_hm + (size_t)n * DMD;
    int w = threadIdx.x >> 5, lane = threadIdx.x & 31;
    __shared__ float logits[EE];
#pragma unroll
    for (int eb = 0; eb < 4; eb++) {
        int e = eb * 4 + w;
        const float* wr = rw + (size_t)e * DMD;
        float p = 0.f;
        for (int d = lane; d < DMD; d += 32) p += row[d] * wr[d];
#pragma unroll
        for (int o = 16; o > 0; o >>= 1) p += __shfl_xor_sync(~0u, p, o);
        if (lane == 0) logits[e] = p;
    }
    __syncthreads();
    if (threadIdx.x == 0) {
        float mx = -1e30f;
        for (int e = 0; e < EE; e++) mx = fmaxf(mx, logits[e]);
        float pr[EE];
        for (int e = 0; e < EE; e++) pr[e] = __expf(logits[e] - mx);
        bool used[EE];
        float wsel[EE];
        for (int e = 0; e < EE; e++) { used[e] = false; wsel[e] = 0.f; }
        float ssum = 0.f;
        for (int t = 0; t < TOPKK; t++) {
            float best = -1.f; int bi = 0;
            for (int e = 0; e < EE; e++)
                if (!used[e] && pr[e] > best) { best = pr[e]; bi = e; }
            used[bi] = true; wsel[bi] = best; ssum += best;
        }
        float inv = 1.f / ssum;
        for (int e = 0; e < EE; e++)
            g_wd[(size_t)n * EE + e] = used[e] ? wsel[e] * inv : 0.f;
    }
}

// -----------------------------------------------------------------------------
extern "C" void kernel_launch(void* const* d_in, const int* in_sizes, int n_in,
                              void* d_out, int out_size)
{
    const float* x    = (const float*)d_in[0];
    const float* cosb = (const float*)d_in[1];
    const float* sinb = (const float*)d_in[2];
    const float* naw  = (const float*)d_in[3];
    const float* q_w  = (const float*)d_in[4];
    const float* k_w  = (const float*)d_in[5];
    const float* v_w  = (const float*)d_in[6];
    const float* qn_w = (const float*)d_in[7];
    const float* kn_w = (const float*)d_in[8];
    const float* o_w  = (const float*)d_in[9];
    const float* nmw  = (const float*)d_in[10];
    const float* rw   = (const float*)d_in[11];
    const float* egw  = (const float*)d_in[12];
    const float* euw  = (const float*)d_in[13];
    const float* edw  = (const float*)d_in[14];
    float* out = (float*)d_out;

    static float *ph = nullptr, *pwqkv, *pqkv, *pao, *phm, *pgate, *pup, *pact;
    static bool init_done = false;
    if (!init_done) {
        cudaGetSymbolAddress((void**)&ph,    g_h);
        cudaGetSymbolAddress((void**)&pwqkv, g_wqkv);
        cudaGetSymbolAddress((void**)&pqkv,  g_qkv);
        cudaGetSymbolAddress((void**)&pao,   g_ao);
        cudaGetSymbolAddress((void**)&phm,   g_hm);
        cudaGetSymbolAddress((void**)&pgate, g_gate);
        cudaGetSymbolAddress((void**)&pup,   g_up);
        cudaGetSymbolAddress((void**)&pact,  g_act);
        cudaFuncSetAttribute(attn_kernel,
                             cudaFuncAttributeMaxDynamicSharedMemorySize, ATTN_SMEM);
        cudaFuncSetAttribute(gemm_ta<0>,
                             cudaFuncAttributeMaxDynamicSharedMemorySize, GEMM_SMEM);
        cudaFuncSetAttribute(gemm_ta<1>,
                             cudaFuncAttributeMaxDynamicSharedMemorySize, GEMM_SMEM);
        cudaFuncSetAttribute(gemm_ta<4>,
                             cudaFuncAttributeMaxDynamicSharedMemorySize, GEMM_SMEM);
        init_done = true;
    }

    // 0) concat qkv weights
    cudaMemcpyAsync(pwqkv, q_w, (size_t)HH * HDD * DMD * 4, cudaMemcpyDeviceToDevice);
    cudaMemcpyAsync(pwqkv + (size_t)HH * HDD * DMD, k_w,
                    (size_t)KVH * HDD * DMD * 4, cudaMemcpyDeviceToDevice);
    cudaMemcpyAsync(pwqkv + (size_t)(HH + KVH) * HDD * DMD, v_w,
                    (size_t)KVH * HDD * DMD * 4, cudaMemcpyDeviceToDevice);

    // 1) pre-attn norm
    rmsnorm_kernel<<<NTOK, 256>>>(x, naw, ph);

    // 2) fused QKV projection (N=5120)
    gemm_ta<0><<<dim3(NQKV / BN, NTOK / BM), 256, GEMM_SMEM>>>(ph, pwqkv, pqkv, nullptr, NQKV, DMD);

    // 3) per-head norm + RoPE + transpose (V transposed to (d,l))
    qkv_post<<<dim3(HH + 2 * KVH, LL, BB), 128>>>(cosb, sinb, qn_w, kn_w);

    // 4) tf32 tensor-core flash attention
    attn_kernel<<<dim3(LL / AQ, HH, BB), 256, ATTN_SMEM>>>();

    // 5) O projection + residual
    gemm_ta<1><<<dim3(DMD / BN, NTOK / BM), 256, GEMM_SMEM>>>(pao, o_w, out, x, DMD, HH * HDD);

    // 6) pre-MLP norm
    rmsnorm_kernel<<<NTOK, 256>>>(out, nmw, phm);

    // 7) router
    router_kernel<<<NTOK, 128>>>(rw);

    // 8) MoE gate and up as flat N=2048 GEMMs
    gemm_ta<0><<<dim3(EE * MII / BN, NTOK / BM), 256, GEMM_SMEM>>>(phm, egw, pgate, nullptr, EE * MII, DMD);
    gemm_ta<0><<<dim3(EE * MII / BN, NTOK / BM), 256, GEMM_SMEM>>>(phm, euw, pup,   nullptr, EE * MII, DMD);

    // 9) act = wd * silu(gate) * up
    moe_act_kernel<<<NTOK, 256>>>();

    // 10) MoE down proj: out += act @ dw^T (expert-blocked B, K=2048)
    gemm_ta<4><<<dim3(DMD / BN, NTOK / BM), 256, GEMM_SMEM>>>(pact, edw, out, nullptr, DMD, EE * MII);
}

// round 17
// speedup vs baseline: 4.7400x; 1.1580x over previous
#include <cuda_runtime.h>
#include <cuda_fp16.h>
#include <cstdint>

#define BB   4
#define LL   1024
#define DMD  2048
#define HH   32
#define KVH  4
#define HDD  128
#define GG   (HH / KVH)
#define EE   16
#define TOPKK 8
#define MII  128
#define NTOK (BB * LL)
#define EPSF 1e-6f
#define NQKV (HH * HDD + 2 * KVH * HDD)   // 5120

// GEMM tiling (tf32 and fp16 share byte geometry: 64B/row chunks)
#define BM 128
#define BN 128
#define BK 16
#define ASTR 20
#define NSTAGE 4
#define GEMM_SMEM (NSTAGE * (BM + BN) * ASTR * 4)   // 81920 bytes

// attention tiling
#define AQ 128
#define AK 64
#define QPAD 132
#define VPAD 68
#define PPAD 68
#define ATTN_SMEM ((AQ * QPAD + 2 * AK * QPAD + HDD * VPAD + 8 * 16 * PPAD) * 4) // 204800

// ---------------- scratch (device globals; IDENTICAL set to round-16) --------
__device__ float g_h   [NTOK * DMD];        // fp32 use ends after QKV GEMM; then fp16 act
__device__ float g_wqkv[NQKV * DMD];
__device__ float g_qkv [NTOK * NQKV];       // fp32 use ends after qkv_post; then fp16 hm
__device__ float g_qt  [NTOK * HH  * HDD];  // fp32 use ends after attention; then fp16 weights
__device__ float g_kt  [NTOK * KVH * HDD];
__device__ float g_vt  [NTOK * KVH * HDD];  // (b,kv,d,l) transposed
__device__ float g_ao  [NTOK * HH  * HDD];
__device__ float g_hm  [NTOK * DMD];
__device__ float g_wd  [NTOK * EE];
__device__ float g_gate[NTOK * EE * MII];
__device__ float g_up  [NTOK * EE * MII];
__device__ float g_act [NTOK * EE * MII];   // unused this round (kept: identical footprint)

// ---------------- helpers ----------------------------------------------------
__device__ __forceinline__ uint32_t s2u(const void* p) {
    return (uint32_t)__cvta_generic_to_shared(p);
}
__device__ __forceinline__ void cp16(uint32_t s, const void* g) {
    asm volatile("cp.async.cg.shared.global [%0], [%1], 16;\n" :: "r"(s), "l"(g));
}
__device__ __forceinline__ void cp_commit() {
    asm volatile("cp.async.commit_group;\n" ::: "memory");
}
__device__ __forceinline__ void cp_wait1() {
    asm volatile("cp.async.wait_group 1;\n" ::: "memory");
}
__device__ __forceinline__ void cp_wait2() {
    asm volatile("cp.async.wait_group 2;\n" ::: "memory");
}
__device__ __forceinline__ void mma8(float* c, const uint32_t* a, const uint32_t* b) {
    asm volatile(
        "mma.sync.aligned.m16n8k8.row.col.f32.tf32.tf32.f32 "
        "{%0,%1,%2,%3}, {%4,%5,%6,%7}, {%8,%9}, {%0,%1,%2,%3};\n"
        : "+f"(c[0]), "+f"(c[1]), "+f"(c[2]), "+f"(c[3])
        : "r"(a[0]), "r"(a[1]), "r"(a[2]), "r"(a[3]), "r"(b[0]), "r"(b[1]));
}
__device__ __forceinline__ void mma16h(float* c, const uint32_t* a, const uint32_t* b) {
    asm volatile(
        "mma.sync.aligned.m16n8k16.row.col.f32.f16.f16.f32 "
        "{%0,%1,%2,%3}, {%4,%5,%6,%7}, {%8,%9}, {%0,%1,%2,%3};\n"
        : "+f"(c[0]), "+f"(c[1]), "+f"(c[2]), "+f"(c[3])
        : "r"(a[0]), "r"(a[1]), "r"(a[2]), "r"(a[3]), "r"(b[0]), "r"(b[1]));
}

// ---------------- fp32 -> fp16 conversion (n % 2048 == 0) --------------------
__global__ __launch_bounds__(256) void cvt_f2h(
    const float* __restrict__ src, __half* __restrict__ dst, int n)
{
    int i = (blockIdx.x * 256 + threadIdx.x) * 8;
    if (i >= n) return;
    float4 a = *(const float4*)(src + i);
    float4 b = *(const float4*)(src + i + 4);
    __half2 h0 = __floats2half2_rn(a.x, a.y);
    __half2 h1 = __floats2half2_rn(a.z, a.w);
    __half2 h2 = __floats2half2_rn(b.x, b.y);
    __half2 h3 = __floats2half2_rn(b.z, b.w);
    uint4 o;
    o.x = *(uint32_t*)&h0; o.y = *(uint32_t*)&h1;
    o.z = *(uint32_t*)&h2; o.w = *(uint32_t*)&h3;
    *(uint4*)(dst + i) = o;
}

// ---------------- tf32 cp.async GEMM (4-stage): C = A @ B^T ------------------
// MODE 0: C = acc   MODE 1: C = aux + acc
template<int MODE>
__global__ __launch_bounds__(256, 2) void gemm_ta(
    const float* __restrict__ A, const float* __restrict__ B,
    float* __restrict__ C, const float* __restrict__ aux, int N, int K)
{
    extern __shared__ float smem[];
    float* As = smem;
    float* Bs = smem + NSTAGE * BM * ASTR;
    const int tid  = threadIdx.x;
    const int row0 = blockIdx.y * BM;
    const int col0 = blockIdx.x * BN;
    const int warp = tid >> 5, lane = tid & 31;
    const int wr = (warp >> 2) * 64, wc = (warp & 3) * 32;
    const int lr = lane >> 2, lc = lane & 3;
    const int ldrow = tid >> 1, ldoff = (tid & 1) * 8;

    const float* Agp = A + (size_t)(row0 + ldrow) * K + ldoff;
    const float* Bgp = B + (size_t)(col0 + ldrow) * K + ldoff;

    float acc[4][4][4] = {};

#define ISSUE(cc) do {                                                         \
        int st_ = (cc) % NSTAGE; int k0_ = (cc) * BK;                          \
        uint32_t sa_ = s2u(&As[st_ * BM * ASTR + ldrow * ASTR + ldoff]);       \
        const float* ag_ = Agp + k0_;                                          \
        cp16(sa_, ag_); cp16(sa_ + 16, ag_ + 4);                               \
        const float* bg_ = Bgp + k0_;                                          \
        uint32_t sb_ = s2u(&Bs[st_ * BN * ASTR + ldrow * ASTR + ldoff]);       \
        cp16(sb_, bg_); cp16(sb_ + 16, bg_ + 4);                               \
    } while (0)

    ISSUE(0); cp_commit();
    ISSUE(1); cp_commit();
    ISSUE(2); cp_commit();

    const int nchunk = K / BK;
    for (int c = 0; c < nchunk; c++) {
        cp_wait2();
        __syncthreads();
        if (c + 3 < nchunk) ISSUE(c + 3);
        cp_commit();

        int st = c % NSTAGE;
        const uint32_t* sA = (const uint32_t*)(As + st * BM * ASTR);
        const uint32_t* sB = (const uint32_t*)(Bs + st * BN * ASTR);
#pragma unroll
        for (int ks = 0; ks < 2; ks++) {
            uint32_t af[4][4], bf[4][2];
#pragma unroll
            for (int mi = 0; mi < 4; mi++) {
                const uint32_t* p = sA + (wr + mi * 16 + lr) * ASTR + ks * 8 + lc;
                af[mi][0] = p[0];
                af[mi][1] = p[8 * ASTR];
                af[mi][2] = p[4];
                af[mi][3] = p[8 * ASTR + 4];
            }
#pragma unroll
            for (int ni = 0; ni < 4; ni++) {
                const uint32_t* p = sB + (wc + ni * 8 + lr) * ASTR + ks * 8 + lc;
                bf[ni][0] = p[0];
                bf[ni][1] = p[4];
            }
#pragma unroll
            for (int mi = 0; mi < 4; mi++)
#pragma unroll
                for (int ni = 0; ni < 4; ni++)
                    mma8(acc[mi][ni], af[mi], bf[ni]);
        }
    }
#undef ISSUE

#pragma unroll
    for (int mi = 0; mi < 4; mi++) {
        int r = row0 + wr + mi * 16 + lr;
#pragma unroll
        for (int ni = 0; ni < 4; ni++) {
            int cc = col0 + wc + ni * 8 + lc * 2;
            size_t i0 = (size_t)r * N + cc;
            size_t i1 = i0 + (size_t)8 * N;
            float2 v0 = make_float2(acc[mi][ni][0], acc[mi][ni][1]);
            float2 v1 = make_float2(acc[mi][ni][2], acc[mi][ni][3]);
            if (MODE == 1) {
                float2 a0 = *(const float2*)(aux + i0);
                float2 a1 = *(const float2*)(aux + i1);
                v0.x += a0.x; v0.y += a0.y; v1.x += a1.x; v1.y += a1.y;
            }
            *(float2*)(C + i0) = v0;
            *(float2*)(C + i1) = v1;
        }
    }
}

// ---------------- fp16 cp.async GEMM (4-stage): C = A @ B^T ------------------
// MODE 0: C = acc   MODE 4: C += acc, B expert-blocked Dw[k>>7][n][k&127]
// K in fp16 elements; chunk = 32 halves = 64B/row (same geometry as tf32).
template<int MODE>
__global__ __launch_bounds__(256) void gemm_hf(
    const __half* __restrict__ A, const __half* __restrict__ B,
    float* __restrict__ C, int N, int K)
{
    extern __shared__ float smem[];
    float* As = smem;
    float* Bs = smem + NSTAGE * BM * ASTR;
    const int tid  = threadIdx.x;
    const int row0 = blockIdx.y * BM;
    const int col0 = blockIdx.x * BN;
    const int warp = tid >> 5, lane = tid & 31;
    const int wr = (warp >> 2) * 64, wc = (warp & 3) * 32;
    const int lr = lane >> 2, lc = lane & 3;
    const int ldrow = tid >> 1;
    const int ldw   = (tid & 1) * 8;     // word offset in smem row
    const int lde   = (tid & 1) * 16;    // half-element offset in gmem row

    const __half* Agp = A + (size_t)(row0 + ldrow) * K + lde;
    const __half* Bgp = B + (size_t)(col0 + ldrow) * K + lde;

    float acc[4][4][4] = {};

#define ISSUEH(cc) do {                                                        \
        int st_ = (cc) % NSTAGE; int k0_ = (cc) * 32;                          \
        uint32_t sa_ = s2u(&As[st_ * BM * ASTR + ldrow * ASTR + ldw]);         \
        const __half* ag_ = Agp + k0_;                                         \
        cp16(sa_, ag_); cp16(sa_ + 16, ag_ + 8);                               \
        const __half* bg_ = (MODE == 4)                                        \
            ? B + (size_t)(k0_ >> 7) * ((size_t)DMD * MII)                     \
                + (size_t)(col0 + ldrow) * MII + (k0_ & 127) + lde             \
            : Bgp + k0_;                                                       \
        uint32_t sb_ = s2u(&Bs[st_ * BN * ASTR + ldrow * ASTR + ldw]);         \
        cp16(sb_, bg_); cp16(sb_ + 16, bg_ + 8);                               \
    } while (0)

    ISSUEH(0); cp_commit();
    ISSUEH(1); cp_commit();
    ISSUEH(2); cp_commit();

    const int nchunk = K / 32;
    for (int c = 0; c < nchunk; c++) {
        cp_wait2();
        __syncthreads();
        if (c + 3 < nchunk) ISSUEH(c + 3);
        cp_commit();

        int st = c % NSTAGE;
        const uint32_t* sA = (const uint32_t*)(As + st * BM * ASTR);
        const uint32_t* sB = (const uint32_t*)(Bs + st * BN * ASTR);
#pragma unroll
        for (int ks = 0; ks < 2; ks++) {        // two k16 halves of the chunk
            uint32_t af[4][4], bf[4][2];
#pragma unroll
            for (int mi = 0; mi < 4; mi++) {
                const uint32_t* p = sA + (wr + mi * 16 + lr) * ASTR + ks * 8 + lc;
                af[mi][0] = p[0];
                af[mi][1] = p[8 * ASTR];
                af[mi][2] = p[4];
                af[mi][3] = p[8 * ASTR + 4];
            }
#pragma unroll
            for (int ni = 0; ni < 4; ni++) {
                const uint32_t* p = sB + (wc + ni * 8 + lr) * ASTR + ks * 8 + lc;
                bf[ni][0] = p[0];
                bf[ni][1] = p[4];
            }
#pragma unroll
            for (int mi = 0; mi < 4; mi++)
#pragma unroll
                for (int ni = 0; ni < 4; ni++)
                    mma16h(acc[mi][ni], af[mi], bf[ni]);
        }
    }
#undef ISSUEH

#pragma unroll
    for (int mi = 0; mi < 4; mi++) {
        int r = row0 + wr + mi * 16 + lr;
#pragma unroll
        for (int ni = 0; ni < 4; ni++) {
            int cc = col0 + wc + ni * 8 + lc * 2;
            size_t i0 = (size_t)r * N + cc;
            size_t i1 = i0 + (size_t)8 * N;
            float2 v0 = make_float2(acc[mi][ni][0], acc[mi][ni][1]);
            float2 v1 = make_float2(acc[mi][ni][2], acc[mi][ni][3]);
            if (MODE == 4) {
                float2 a0 = *(const float2*)(C + i0);
                float2 a1 = *(const float2*)(C + i1);
                v0.x += a0.x; v0.y += a0.y; v1.x += a1.x; v1.y += a1.y;
            }
            *(float2*)(C + i0) = v0;
            *(float2*)(C + i1) = v1;
        }
    }
}

// -------- MoE elementwise: act_h = wd * silu(gate) * up  (writes fp16) -------
__global__ __launch_bounds__(256) void moe_act_kernel(__half* __restrict__ ah_base)
{
    int n = blockIdx.x;
    const float4* gp = (const float4*)(g_gate + (size_t)n * EE * MII);
    const float4* up = (const float4*)(g_up   + (size_t)n * EE * MII);
    const float*  wdp = g_wd + (size_t)n * EE;
    __half* ah = ah_base + (size_t)n * EE * MII;
#pragma unroll
    for (int t = 0; t < 2; t++) {
        int i = threadIdx.x + t * 256;       // float4 index; col = i*4
        float w = wdp[(i * 4) >> 7];
        float4 g = gp[i], u = up[i];
        float o0 = w * (g.x / (1.f + __expf(-g.x))) * u.x;
        float o1 = w * (g.y / (1.f + __expf(-g.y))) * u.y;
        float o2 = w * (g.z / (1.f + __expf(-g.z))) * u.z;
        float o3 = w * (g.w / (1.f + __expf(-g.w))) * u.w;
        __half2 h0 = __floats2half2_rn(o0, o1);
        __half2 h1 = __floats2half2_rn(o2, o3);
        uint2 o;
        o.x = *(uint32_t*)&h0; o.y = *(uint32_t*)&h1;
        *(uint2*)(ah + i * 4) = o;
    }
}

// ---------------- row RMSNorm over DM ----------------------------------------
__global__ __launch_bounds__(256) void rmsnorm_kernel(
    const float* __restrict__ x, const float* __restrict__ w, float* __restrict__ y)
{
    int row = blockIdx.x;
    const float* xr = x + (size_t)row * DMD;
    float ss = 0.f;
    for (int d = threadIdx.x; d < DMD; d += 256) { float v = xr[d]; ss += v * v; }
    __shared__ float red[8];
#pragma unroll
    for (int o = 16; o > 0; o >>= 1) ss += __shfl_xor_sync(~0u, ss, o);
    if ((threadIdx.x & 31) == 0) red[threadIdx.x >> 5] = ss;
    __syncthreads();
    if (threadIdx.x < 8) {
        float t = red[threadIdx.x];
#pragma unroll
        for (int o = 4; o > 0; o >>= 1) t += __shfl_xor_sync(0xffu, t, o);
        if (threadIdx.x == 0) red[0] = t;
    }
    __syncthreads();
    float scale = rsqrtf(red[0] / (float)DMD + EPSF);
    for (int d = threadIdx.x; d < DMD; d += 256)
        y[(size_t)row * DMD + d] = xr[d] * scale * w[d];
}

// -------- per-head RMSNorm + RoPE + transpose; V transposed to (d, l) --------
__global__ __launch_bounds__(128) void qkv_post(
    const float* __restrict__ cosb, const float* __restrict__ sinb,
    const float* __restrict__ qn_w, const float* __restrict__ kn_w)
{
    int b = blockIdx.z, l = blockIdx.y, rr = blockIdx.x;
    int d = threadIdx.x;
    int n = b * LL + l;
    __shared__ float buf[HDD];
    __shared__ float red[4];

    const float* src; float* dst; const float* nw;
    if (rr < HH) {
        src = g_qkv + (size_t)n * NQKV + rr * HDD;
        dst = g_qt + ((size_t)(b * HH + rr) * LL + l) * HDD;
        nw = qn_w;
    } else if (rr < HH + KVH) {
        int kv = rr - HH;
        src = g_qkv + (size_t)n * NQKV + HH * HDD + kv * HDD;
        dst = g_kt + ((size_t)(b * KVH + kv) * LL + l) * HDD;
        nw = kn_w;
    } else {
        int kv = rr - HH - KVH;
        g_vt[((size_t)(b * KVH + kv) * HDD + d) * LL + l] =
            g_qkv[(size_t)n * NQKV + (HH + KVH) * HDD + kv * HDD + d];
        return;
    }
    float v = src[d];
    float ss = v * v;
#pragma unroll
    for (int o = 16; o > 0; o >>= 1) ss += __shfl_xor_sync(~0u, ss, o);
    if ((d & 31) == 0) red[d >> 5] = ss;
    __syncthreads();
    float tot = red[0] + red[1] + red[2] + red[3];
    float nv = v * rsqrtf(tot / (float)HDD + EPSF) * nw[d];
    buf[d] = nv;
    __syncthreads();
    float other = (d < HDD / 2) ? -buf[d + HDD / 2] : buf[d - HDD / 2];
    float c = cosb[(size_t)n * HDD + d];
    float s = sinb[(size_t)n * HDD + d];
    dst[d] = c * nv + s * other;
}

// ---------------- tf32 tensor-core flash attention (causal, GQA) -------------
__global__ __launch_bounds__(256) void attn_kernel()
{
    extern __shared__ float sm[];
    float* Qs  = sm;                        // [128][132]
    float* Ksm = Qs + AQ * QPAD;            // [2][64][132]
    float* Vsm = Ksm + 2 * AK * QPAD;       // [128][68]
    float* Psm = Vsm + HDD * VPAD;          // [8][16][68]

    const int tid = threadIdx.x;
    const int wid = tid >> 5, lane = tid & 31;
    const int lr = lane >> 2, lc = lane & 3;
    const int b = blockIdx.z, h = blockIdx.y;
    const int q0 = blockIdx.x * AQ;
    const int kv = h / GG;
    const int wq0 = wid * 16;
    const float SCALE = 0.08838834764831845f;

    const float* Qg = g_qt + ((size_t)(b * HH + h) * LL + q0) * HDD;
    const float* Kg = g_kt + ((size_t)(b * KVH + kv) * LL) * HDD;
    const float* Vg = g_vt + ((size_t)(b * KVH + kv) * HDD) * LL;

    {
        int r = tid >> 1, half = (tid & 1) * 64;
        const float* src = Qg + (size_t)r * HDD + half;
        uint32_t dst = s2u(Qs + r * QPAD + half);
#pragma unroll
        for (int j = 0; j < 16; j++) cp16(dst + j * 16, src + j * 4);
    }
    {
        int r = tid >> 2, q4 = (tid & 3) * 32;
        const float* src = Kg + (size_t)r * HDD + q4;
        uint32_t dst = s2u(Ksm + r * QPAD + q4);
#pragma unroll
        for (int j = 0; j < 8; j++) cp16(dst + j * 16, src + j * 4);
    }
    cp_commit();

    float oacc[16][4];
#pragma unroll
    for (int i = 0; i < 16; i++)
#pragma unroll
        for (int j = 0; j < 4; j++) oacc[i][j] = 0.f;
    float m0 = -1e30f, m1 = -1e30f, l0 = 0.f, l1 = 0.f;

    const int ntile = q0 / AK + 2;
    for (int kt = 0; kt < ntile; kt++) {
        int k0 = kt * AK;
        __syncthreads();
        {
            int r = tid >> 1, half = (tid & 1) * 32;
            const float* src = Vg + (size_t)r * LL + k0 + half;
            uint32_t dst = s2u(Vsm + r * VPAD + half);
#pragma unroll
            for (int j = 0; j < 8; j++) cp16(dst + j * 16, src + j * 4);
        }
        cp_commit();
        if (kt + 1 < ntile) {
            int r = tid >> 2, q4 = (tid & 3) * 32;
            const float* src = Kg + (size_t)(k0 + AK + r) * HDD + q4;
            uint32_t dst = s2u(Ksm + ((kt + 1) & 1) * AK * QPAD + r * QPAD + q4);
#pragma unroll
            for (int j = 0; j < 8; j++) cp16(dst + j * 16, src + j * 4);
        }
        cp_commit();
        cp_wait2();
        __syncthreads();

        const uint32_t* sQ = (const uint32_t*)Qs;
        const uint32_t* sK = (const uint32_t*)(Ksm + (kt & 1) * AK * QPAD);
        float sacc[8][4] = {};
#pragma unroll
        for (int ks = 0; ks < 16; ks++) {
            uint32_t a[4];
            const uint32_t* qp = sQ + (wq0 + lr) * QPAD + ks * 8 + lc;
            a[0] = qp[0]; a[1] = qp[8 * QPAD]; a[2] = qp[4]; a[3] = qp[8 * QPAD + 4];
#pragma unroll
            for (int ni = 0; ni < 8; ni++) {
                uint32_t bb[2];
                const uint32_t* kp = sK + (ni * 8 + lr) * QPAD + ks * 8 + lc;
                bb[0] = kp[0]; bb[1] = kp[4];
                mma8(sacc[ni], a, bb);
            }
        }

        const int grow0 = q0 + wq0 + lr;
        const int grow1 = grow0 + 8;
        const bool maskt = (k0 + AK > q0);
        float mx0 = -1e30f, mx1 = -1e30f;
#pragma unroll
        for (int ni = 0; ni < 8; ni++) {
            int gc = k0 + ni * 8 + 2 * lc;
            float s0 = sacc[ni][0] * SCALE, s1 = sacc[ni][1] * SCALE;
            float s2 = sacc[ni][2] * SCALE, s3 = sacc[ni][3] * SCALE;
            if (maskt) {
                if (gc     > grow0) s0 = -1e30f;
                if (gc + 1 > grow0) s1 = -1e30f;
                if (gc     > grow1) s2 = -1e30f;
                if (gc + 1 > grow1) s3 = -1e30f;
            }
            sacc[ni][0] = s0; sacc[ni][1] = s1; sacc[ni][2] = s2; sacc[ni][3] = s3;
            mx0 = fmaxf(mx0, fmaxf(s0, s1));
            mx1 = fmaxf(mx1, fmaxf(s2, s3));
        }
        mx0 = fmaxf(mx0, __shfl_xor_sync(~0u, mx0, 1));
        mx0 = fmaxf(mx0, __shfl_xor_sync(~0u, mx0, 2));
        mx1 = fmaxf(mx1, __shfl_xor_sync(~0u, mx1, 1));
        mx1 = fmaxf(mx1, __shfl_xor_sync(~0u, mx1, 2));
        float mn0 = fmaxf(m0, mx0), mn1 = fmaxf(m1, mx1);
        float al0 = __expf(m0 - mn0), al1 = __expf(m1 - mn1);
        m0 = mn0; m1 = mn1;

        float* Pw = Psm + wid * 16 * PPAD;
        float sum0 = 0.f, sum1 = 0.f;
#pragma unroll
        for (int ni = 0; ni < 8; ni++) {
            float p0 = __expf(sacc[ni][0] - mn0);
            float p1 = __expf(sacc[ni][1] - mn0);
            float p2 = __expf(sacc[ni][2] - mn1);
            float p3 = __expf(sacc[ni][3] - mn1);
            sum0 += p0 + p1; sum1 += p2 + p3;
            *(float2*)(Pw + lr * PPAD + ni * 8 + 2 * lc)       = make_float2(p0, p1);
            *(float2*)(Pw + (lr + 8) * PPAD + ni * 8 + 2 * lc) = make_float2(p2, p3);
        }
        sum0 += __shfl_xor_sync(~0u, sum0, 1);
        sum0 += __shfl_xor_sync(~0u, sum0, 2);
        sum1 += __shfl_xor_sync(~0u, sum1, 1);
        sum1 += __shfl_xor_sync(~0u, sum1, 2);
        l0 = l0 * al0 + sum0;
        l1 = l1 * al1 + sum1;
#pragma unroll
        for (int ni = 0; ni < 16; ni++) {
            oacc[ni][0] *= al0; oacc[ni][1] *= al0;
            oacc[ni][2] *= al1; oacc[ni][3] *= al1;
        }

        cp_wait1();
        __syncthreads();

        const uint32_t* sP = (const uint32_t*)Pw;
        const uint32_t* sV = (const uint32_t*)Vsm;
#pragma unroll
        for (int ks = 0; ks < 8; ks++) {
            uint32_t a[4];
            const uint32_t* pp = sP + lr * PPAD + ks * 8 + lc;
            a[0] = pp[0]; a[1] = pp[8 * PPAD]; a[2] = pp[4]; a[3] = pp[8 * PPAD + 4];
#pragma unroll
            for (int ni = 0; ni < 16; ni++) {
                uint32_t bb[2];
                const uint32_t* vp = sV + (ni * 8 + lr) * VPAD + ks * 8 + lc;
                bb[0] = vp[0]; bb[1] = vp[4];
                mma8(oacc[ni], a, bb);
            }
        }
    }

    float inv0 = 1.f / l0, inv1 = 1.f / l1;
    int row0g = q0 + wq0 + lr;
    float* O0 = g_ao + ((size_t)(b * LL + row0g) * HH + h) * HDD;
    float* O1 = g_ao + ((size_t)(b * LL + row0g + 8) * HH + h) * HDD;
#pragma unroll
    for (int ni = 0; ni < 16; ni++) {
        int d = ni * 8 + 2 * lc;
        *(float2*)(O0 + d) = make_float2(oacc[ni][0] * inv0, oacc[ni][1] * inv0);
        *(float2*)(O1 + d) = make_float2(oacc[ni][2] * inv1, oacc[ni][3] * inv1);
    }
}

// ---------------- router ------------------------------------------------------
__global__ __launch_bounds__(128) void router_kernel(const float* __restrict__ rw)
{
    int n = blockIdx.x;
    const float* row = g_hm + (size_t)n * DMD;
    int w = threadIdx.x >> 5, lane = threadIdx.x & 31;
    __shared__ float logits[EE];
#pragma unroll
    for (int eb = 0; eb < 4; eb++) {
        int e = eb * 4 + w;
        const float* wr = rw + (size_t)e * DMD;
        float p = 0.f;
        for (int d = lane; d < DMD; d += 32) p += row[d] * wr[d];
#pragma unroll
        for (int o = 16; o > 0; o >>= 1) p += __shfl_xor_sync(~0u, p, o);
        if (lane == 0) logits[e] = p;
    }
    __syncthreads();
    if (threadIdx.x == 0) {
        float mx = -1e30f;
        for (int e = 0; e < EE; e++) mx = fmaxf(mx, logits[e]);
        float pr[EE];
        for (int e = 0; e < EE; e++) pr[e] = __expf(logits[e] - mx);
        bool used[EE];
        float wsel[EE];
        for (int e = 0; e < EE; e++) { used[e] = false; wsel[e] = 0.f; }
        float ssum = 0.f;
        for (int t = 0; t < TOPKK; t++) {
            float best = -1.f; int bi = 0;
            for (int e = 0; e < EE; e++)
                if (!used[e] && pr[e] > best) { best = pr[e]; bi = e; }
            used[bi] = true; wsel[bi] = best; ssum += best;
        }
        float inv = 1.f / ssum;
        for (int e = 0; e < EE; e++)
            g_wd[(size_t)n * EE + e] = used[e] ? wsel[e] * inv : 0.f;
    }
}

// -----------------------------------------------------------------------------
extern "C" void kernel_launch(void* const* d_in, const int* in_sizes, int n_in,
                              void* d_out, int out_size)
{
    const float* x    = (const float*)d_in[0];
    const float* cosb = (const float*)d_in[1];
    const float* sinb = (const float*)d_in[2];
    const float* naw  = (const float*)d_in[3];
    const float* q_w  = (const float*)d_in[4];
    const float* k_w  = (const float*)d_in[5];
    const float* v_w  = (const float*)d_in[6];
    const float* qn_w = (const float*)d_in[7];
    const float* kn_w = (const float*)d_in[8];
    const float* o_w  = (const float*)d_in[9];
    const float* nmw  = (const float*)d_in[10];
    const float* rw   = (const float*)d_in[11];
    const float* egw  = (const float*)d_in[12];
    const float* euw  = (const float*)d_in[13];
    const float* edw  = (const float*)d_in[14];
    float* out = (float*)d_out;

    static float *ph = nullptr, *pwqkv, *pqkv, *pqt, *pao, *phm, *pgate, *pup;
    static __half *phmh, *pegwh, *peuwh, *pedwh, *pacth;
    static bool init_done = false;
    if (!init_done) {
        cudaGetSymbolAddress((void**)&ph,    g_h);
        cudaGetSymbolAddress((void**)&pwqkv, g_wqkv);
        cudaGetSymbolAddress((void**)&pqkv,  g_qkv);
        cudaGetSymbolAddress((void**)&pqt,   g_qt);
        cudaGetSymbolAddress((void**)&pao,   g_ao);
        cudaGetSymbolAddress((void**)&phm,   g_hm);
        cudaGetSymbolAddress((void**)&pgate, g_gate);
        cudaGetSymbolAddress((void**)&pup,   g_up);
        // fp16 views aliased into scratch that is dead at time of use:
        phmh  = (__half*)pqkv;                         // g_qkv free after qkv_post
        pegwh = (__half*)pqt;                          // g_qt free after attention
        peuwh = pegwh + (size_t)EE * MII * DMD;
        pedwh = peuwh + (size_t)EE * MII * DMD;        // 25.2MB of 67.1MB
        pacth = (__half*)ph;                           // g_h free after QKV GEMM
        cudaFuncSetAttribute(attn_kernel,
                             cudaFuncAttributeMaxDynamicSharedMemorySize, ATTN_SMEM);
        cudaFuncSetAttribute(gemm_ta<0>,
                             cudaFuncAttributeMaxDynamicSharedMemorySize, GEMM_SMEM);
        cudaFuncSetAttribute(gemm_ta<1>,
                             cudaFuncAttributeMaxDynamicSharedMemorySize, GEMM_SMEM);
        cudaFuncSetAttribute(gemm_hf<0>,
                             cudaFuncAttributeMaxDynamicSharedMemorySize, GEMM_SMEM);
        cudaFuncSetAttribute(gemm_hf<4>,
                             cudaFuncAttributeMaxDynamicSharedMemorySize, GEMM_SMEM);
        init_done = true;
    }

    // 0) concat qkv weights
    cudaMemcpyAsync(pwqkv, q_w, (size_t)HH * HDD * DMD * 4, cudaMemcpyDeviceToDevice);
    cudaMemcpyAsync(pwqkv + (size_t)HH * HDD * DMD, k_w,
                    (size_t)KVH * HDD * DMD * 4, cudaMemcpyDeviceToDevice);
    cudaMemcpyAsync(pwqkv + (size_t)(HH + KVH) * HDD * DMD, v_w,
                    (size_t)KVH * HDD * DMD * 4, cudaMemcpyDeviceToDevice);

    // 1) pre-attn norm
    rmsnorm_kernel<<<NTOK, 256>>>(x, naw, ph);

    // 2) fused QKV projection (tf32, N=5120)
    gemm_ta<0><<<dim3(NQKV / BN, NTOK / BM), 256, GEMM_SMEM>>>(ph, pwqkv, pqkv, nullptr, NQKV, DMD);

    // 3) per-head norm + RoPE + transpose (V transposed to (d,l))
    qkv_post<<<dim3(HH + 2 * KVH, LL, BB), 128>>>(cosb, sinb, qn_w, kn_w);

    // 4) tf32 tensor-core flash attention
    attn_kernel<<<dim3(LL / AQ, HH, BB), 256, ATTN_SMEM>>>();

    // 4b) convert MoE weights to fp16 into g_qt space (free after attention)
    {
        int nw1 = EE * MII * DMD;             // 4,194,304
        cvt_f2h<<<nw1 / (256 * 8), 256>>>(egw, pegwh, nw1);
        cvt_f2h<<<nw1 / (256 * 8), 256>>>(euw, peuwh, nw1);
        cvt_f2h<<<nw1 / (256 * 8), 256>>>(edw, pedwh, nw1);
    }

    // 5) O projection + residual (tf32)
    gemm_ta<1><<<dim3(DMD / BN, NTOK / BM), 256, GEMM_SMEM>>>(pao, o_w, out, x, DMD, HH * HDD);

    // 6) pre-MLP norm + fp16 copy into g_qkv space (free after step 3)
    rmsnorm_kernel<<<NTOK, 256>>>(out, nmw, phm);
    {
        int nh = NTOK * DMD;
        cvt_f2h<<<nh / (256 * 8), 256>>>(phm, phmh, nh);
    }

    // 7) router (fp32)
    router_kernel<<<NTOK, 128>>>(rw);

    // 8) MoE gate and up (fp16, N=2048)
    gemm_hf<0><<<dim3(EE * MII / BN, NTOK / BM), 256, GEMM_SMEM>>>(phmh, pegwh, pgate, EE * MII, DMD);
    gemm_hf<0><<<dim3(EE * MII / BN, NTOK / BM), 256, GEMM_SMEM>>>(phmh, peuwh, pup,   EE * MII, DMD);

    // 9) act_h = wd * silu(gate) * up  (fp16 into g_h space, free after step 2)
    moe_act_kernel<<<NTOK, 256>>>(pacth);

    // 10) MoE down proj (fp16, expert-blocked B, K=2048): out += act @ dw^T
    gemm_hf<4><<<dim3(DMD / BN, NTOK / BM), 256, GEMM_SMEM>>>(pacth, pedwh, out, DMD, EE * MII);
}